// round 1
// baseline (speedup 1.0000x reference)
#include <cuda_runtime.h>
#include <math.h>

// Problem constants
#define B_   2
#define S_   2048
#define DM_  1024
#define H_   16
#define DH_  64
#define M_   (B_ * S_)          // 4096 rows
#define ROWSTRIDE 3072          // qkv row stride (3*DM_)

// Scratch (allocation-free rule: __device__ globals)
__device__ float g_qkv[(size_t)M_ * 3 * DM_];   // [4096][3][16][64]
__device__ float g_attn[(size_t)M_ * DM_];      // [B,S,Dm] attention output

// ---------------------------------------------------------------------------
// SGEMM: C[M,N] = A[M,K] @ B[N,K]^T + bias[N]
// BM=BN=128, BK=16, 256 threads, 8x8 per thread (4+4 split microtile)
// ---------------------------------------------------------------------------
__global__ __launch_bounds__(256) void sgemm_nt_bias(
    const float* __restrict__ A, const float* __restrict__ Bm,
    const float* __restrict__ bias, float* __restrict__ C,
    int M, int N, int K)
{
    __shared__ float As[16][132];
    __shared__ float Bs[16][132];
    const int tid = threadIdx.x;
    const int tx = tid & 15, ty = tid >> 4;
    const int bm = blockIdx.y * 128, bn = blockIdx.x * 128;

    float acc[8][8];
#pragma unroll
    for (int i = 0; i < 8; i++)
#pragma unroll
        for (int j = 0; j < 8; j++) acc[i][j] = 0.f;

    for (int k0 = 0; k0 < K; k0 += 16) {
#pragma unroll
        for (int i = 0; i < 2; i++) {
            int L = i * 256 + tid;              // 0..511 float4 slots
            int row = L >> 2, c4 = (L & 3) << 2;
            float4 v = *(const float4*)(A + (size_t)(bm + row) * K + k0 + c4);
            As[c4 + 0][row] = v.x; As[c4 + 1][row] = v.y;
            As[c4 + 2][row] = v.z; As[c4 + 3][row] = v.w;
            float4 w = *(const float4*)(Bm + (size_t)(bn + row) * K + k0 + c4);
            Bs[c4 + 0][row] = w.x; Bs[c4 + 1][row] = w.y;
            Bs[c4 + 2][row] = w.z; Bs[c4 + 3][row] = w.w;
        }
        __syncthreads();
#pragma unroll
        for (int k = 0; k < 16; k++) {
            float a0[4], a1[4], b0[4], b1[4];
            *(float4*)a0 = *(const float4*)&As[k][4 * ty];
            *(float4*)a1 = *(const float4*)&As[k][64 + 4 * ty];
            *(float4*)b0 = *(const float4*)&Bs[k][4 * tx];
            *(float4*)b1 = *(const float4*)&Bs[k][64 + 4 * tx];
#pragma unroll
            for (int i = 0; i < 4; i++)
#pragma unroll
                for (int j = 0; j < 4; j++) {
                    acc[i][j]         = fmaf(a0[i], b0[j], acc[i][j]);
                    acc[i][j + 4]     = fmaf(a0[i], b1[j], acc[i][j + 4]);
                    acc[i + 4][j]     = fmaf(a1[i], b0[j], acc[i + 4][j]);
                    acc[i + 4][j + 4] = fmaf(a1[i], b1[j], acc[i + 4][j + 4]);
                }
        }
        __syncthreads();
    }

#pragma unroll
    for (int gi = 0; gi < 2; gi++)
#pragma unroll
        for (int i = 0; i < 4; i++) {
            int r = bm + gi * 64 + 4 * ty + i;
#pragma unroll
            for (int gj = 0; gj < 2; gj++) {
                int c = bn + gj * 64 + 4 * tx;
                float4 bv = *(const float4*)(bias + c);
                float4 o;
                o.x = acc[gi * 4 + i][gj * 4 + 0] + bv.x;
                o.y = acc[gi * 4 + i][gj * 4 + 1] + bv.y;
                o.z = acc[gi * 4 + i][gj * 4 + 2] + bv.z;
                o.w = acc[gi * 4 + i][gj * 4 + 3] + bv.w;
                *(float4*)(C + (size_t)r * N + c) = o;
            }
        }
}

// ---------------------------------------------------------------------------
// Partial RoPE, in-place on q and k slices of g_qkv.
// rot_dim = 32 of 64; interleaved pairs (2i, 2i+1); pair freq = 10000^(-i/16).
// ---------------------------------------------------------------------------
__global__ __launch_bounds__(256) void rope_kernel(float* __restrict__ qkv)
{
    int tid = blockIdx.x * blockDim.x + threadIdx.x;
    // total = 4096 rows * 2 (q,k) * 16 heads * 16 pairs = 2,097,152
    if (tid >= M_ * 2 * H_ * 16) return;
    int pair = tid & 15;
    int h    = (tid >> 4) & 15;
    int qk   = (tid >> 8) & 1;
    int row  = tid >> 9;                 // 0..4095 (= b*S + s)
    int s    = row & (S_ - 1);

    float inv_freq = (float)pow(10000.0, -(double)pair / 16.0);
    float ang = (float)s * inv_freq;
    float sn, cs;
    sincosf(ang, &sn, &cs);

    float* p = qkv + (size_t)row * ROWSTRIDE + qk * DM_ + h * DH_ + 2 * pair;
    float x1 = p[0], x2 = p[1];
    p[0] = x1 * cs - x2 * sn;
    p[1] = x2 * cs + x1 * sn;
}

// ---------------------------------------------------------------------------
// Flash attention (fp32): per block one (b,h) and 128 queries.
// KV tiles of 64, online softmax, 256 threads (16x16), 8x4 microtile.
// ---------------------------------------------------------------------------
#define QT 128
#define KT 64
#define QSTRIDE 132
#define KSTRIDE 68
#define FLASH_SMEM_FLOATS (64*QSTRIDE + 64*KSTRIDE + 64*KSTRIDE + 128*KSTRIDE)

__global__ __launch_bounds__(256) void flash_attn(
    const float* __restrict__ qkv, float* __restrict__ outp)
{
    extern __shared__ float sm[];
    float* Qts = sm;                        // [64 d][132 m]  (transposed)
    float* Kts = Qts + 64 * QSTRIDE;        // [64 d][68 n]   (transposed)
    float* Vs  = Kts + 64 * KSTRIDE;        // [64 j][68 d]   (natural)
    float* Ps  = Vs  + 64 * KSTRIDE;        // [128 m][68 j]  (natural)

    const int tid = threadIdx.x;
    const int tx = tid & 15, ty = tid >> 4;
    const int bh = blockIdx.y;
    const int bb = bh >> 4, h = bh & 15;
    const int q0 = blockIdx.x * QT;

    const float* qbase = qkv + (size_t)bb * S_ * ROWSTRIDE + h * DH_;
    const float* kbase = qbase + DM_;
    const float* vbase = qbase + 2 * DM_;

    // Load Q tile transposed: rows q0..q0+127, dims 0..63
#pragma unroll
    for (int i = 0; i < 8; i++) {
        int L = i * 256 + tid;              // 0..2047 float4 slots
        int row = L >> 4;
        int d4 = (L & 15) << 2;
        float4 v = *(const float4*)(qbase + (size_t)(q0 + row) * ROWSTRIDE + d4);
        Qts[(d4 + 0) * QSTRIDE + row] = v.x;
        Qts[(d4 + 1) * QSTRIDE + row] = v.y;
        Qts[(d4 + 2) * QSTRIDE + row] = v.z;
        Qts[(d4 + 3) * QSTRIDE + row] = v.w;
    }

    float mrow[2][4], lrow[2][4], acc[2][4][4];
#pragma unroll
    for (int g = 0; g < 2; g++)
#pragma unroll
        for (int a = 0; a < 4; a++) {
            mrow[g][a] = -INFINITY;
            lrow[g][a] = 0.f;
#pragma unroll
            for (int j = 0; j < 4; j++) acc[g][a][j] = 0.f;
        }

    const float scale = 0.125f;             // 1/sqrt(64)

    for (int t = 0; t < S_ / KT; t++) {
        // Load K tile transposed + V tile natural
#pragma unroll
        for (int i = 0; i < 4; i++) {
            int L = i * 256 + tid;          // 0..1023 float4 slots
            int row = L >> 4;               // j within tile
            int d4 = (L & 15) << 2;
            const size_t goff = (size_t)(t * KT + row) * ROWSTRIDE + d4;
            float4 kv = *(const float4*)(kbase + goff);
            Kts[(d4 + 0) * KSTRIDE + row] = kv.x;
            Kts[(d4 + 1) * KSTRIDE + row] = kv.y;
            Kts[(d4 + 2) * KSTRIDE + row] = kv.z;
            Kts[(d4 + 3) * KSTRIDE + row] = kv.w;
            float4 vv = *(const float4*)(vbase + goff);
            *(float4*)&Vs[row * KSTRIDE + d4] = vv;
        }
        __syncthreads();

        // S = Q @ K^T
        float s[2][4][4];
#pragma unroll
        for (int g = 0; g < 2; g++)
#pragma unroll
            for (int a = 0; a < 4; a++)
#pragma unroll
                for (int j = 0; j < 4; j++) s[g][a][j] = 0.f;

#pragma unroll 8
        for (int k = 0; k < 64; k++) {
            float qa[4], qb[4], kk[4];
            *(float4*)qa = *(const float4*)&Qts[k * QSTRIDE + 4 * ty];
            *(float4*)qb = *(const float4*)&Qts[k * QSTRIDE + 64 + 4 * ty];
            *(float4*)kk = *(const float4*)&Kts[k * KSTRIDE + 4 * tx];
#pragma unroll
            for (int a = 0; a < 4; a++)
#pragma unroll
                for (int j = 0; j < 4; j++) {
                    s[0][a][j] = fmaf(qa[a], kk[j], s[0][a][j]);
                    s[1][a][j] = fmaf(qb[a], kk[j], s[1][a][j]);
                }
        }

        // Online softmax + write P
#pragma unroll
        for (int g = 0; g < 2; g++)
#pragma unroll
            for (int a = 0; a < 4; a++) {
                float rm = fmaxf(fmaxf(s[g][a][0], s[g][a][1]),
                                 fmaxf(s[g][a][2], s[g][a][3]));
#pragma unroll
                for (int off = 8; off >= 1; off >>= 1)
                    rm = fmaxf(rm, __shfl_xor_sync(0xffffffffu, rm, off));
                float mnew = fmaxf(mrow[g][a], rm * scale);
                float corr = __expf(mrow[g][a] - mnew);
                float rowsum = 0.f;
                float4 p4;
                p4.x = __expf(fmaf(s[g][a][0], scale, -mnew));
                p4.y = __expf(fmaf(s[g][a][1], scale, -mnew));
                p4.z = __expf(fmaf(s[g][a][2], scale, -mnew));
                p4.w = __expf(fmaf(s[g][a][3], scale, -mnew));
                rowsum = p4.x + p4.y + p4.z + p4.w;
#pragma unroll
                for (int off = 8; off >= 1; off >>= 1)
                    rowsum += __shfl_xor_sync(0xffffffffu, rowsum, off);
                lrow[g][a] = lrow[g][a] * corr + rowsum;
                mrow[g][a] = mnew;
#pragma unroll
                for (int j = 0; j < 4; j++) acc[g][a][j] *= corr;
                int r = 64 * g + 4 * ty + a;
                *(float4*)&Ps[r * KSTRIDE + 4 * tx] = p4;
            }
        __syncthreads();

        // O += P @ V
#pragma unroll 2
        for (int j = 0; j < 64; j += 4) {
            float4 v0 = *(const float4*)&Vs[(j + 0) * KSTRIDE + 4 * tx];
            float4 v1 = *(const float4*)&Vs[(j + 1) * KSTRIDE + 4 * tx];
            float4 v2 = *(const float4*)&Vs[(j + 2) * KSTRIDE + 4 * tx];
            float4 v3 = *(const float4*)&Vs[(j + 3) * KSTRIDE + 4 * tx];
#pragma unroll
            for (int g = 0; g < 2; g++)
#pragma unroll
                for (int a = 0; a < 4; a++) {
                    int r = 64 * g + 4 * ty + a;
                    float4 p4 = *(const float4*)&Ps[r * KSTRIDE + j];
                    acc[g][a][0] = fmaf(p4.x, v0.x, acc[g][a][0]);
                    acc[g][a][1] = fmaf(p4.x, v0.y, acc[g][a][1]);
                    acc[g][a][2] = fmaf(p4.x, v0.z, acc[g][a][2]);
                    acc[g][a][3] = fmaf(p4.x, v0.w, acc[g][a][3]);
                    acc[g][a][0] = fmaf(p4.y, v1.x, acc[g][a][0]);
                    acc[g][a][1] = fmaf(p4.y, v1.y, acc[g][a][1]);
                    acc[g][a][2] = fmaf(p4.y, v1.z, acc[g][a][2]);
                    acc[g][a][3] = fmaf(p4.y, v1.w, acc[g][a][3]);
                    acc[g][a][0] = fmaf(p4.z, v2.x, acc[g][a][0]);
                    acc[g][a][1] = fmaf(p4.z, v2.y, acc[g][a][1]);
                    acc[g][a][2] = fmaf(p4.z, v2.z, acc[g][a][2]);
                    acc[g][a][3] = fmaf(p4.z, v2.w, acc[g][a][3]);
                    acc[g][a][0] = fmaf(p4.w, v3.x, acc[g][a][0]);
                    acc[g][a][1] = fmaf(p4.w, v3.y, acc[g][a][1]);
                    acc[g][a][2] = fmaf(p4.w, v3.z, acc[g][a][2]);
                    acc[g][a][3] = fmaf(p4.w, v3.w, acc[g][a][3]);
                }
        }
        __syncthreads();
    }

    // Epilogue: normalize and write to [B,S,Dm]
#pragma unroll
    for (int g = 0; g < 2; g++)
#pragma unroll
        for (int a = 0; a < 4; a++) {
            float inv = 1.f / lrow[g][a];
            int r = q0 + 64 * g + 4 * ty + a;
            float4 o;
            o.x = acc[g][a][0] * inv;
            o.y = acc[g][a][1] * inv;
            o.z = acc[g][a][2] * inv;
            o.w = acc[g][a][3] * inv;
            *(float4*)(outp + ((size_t)bb * S_ + r) * DM_ + h * DH_ + 4 * tx) = o;
        }
}

// ---------------------------------------------------------------------------
extern "C" void kernel_launch(void* const* d_in, const int* in_sizes, int n_in,
                              void* d_out, int out_size)
{
    const float* x    = (const float*)d_in[0];
    const float* Wqkv = (const float*)d_in[1];
    const float* bqkv = (const float*)d_in[2];
    const float* Wout = (const float*)d_in[3];
    const float* bout = (const float*)d_in[4];
    float* out = (float*)d_out;

    float *qkv = nullptr, *attn = nullptr;
    cudaGetSymbolAddress((void**)&qkv, g_qkv);
    cudaGetSymbolAddress((void**)&attn, g_attn);

    // 1) QKV projection: [4096,1024] @ [3072,1024]^T + bias
    dim3 g1(3072 / 128, 4096 / 128);
    sgemm_nt_bias<<<g1, 256>>>(x, Wqkv, bqkv, qkv, M_, 3 * DM_, DM_);

    // 2) RoPE on q,k (in place)
    rope_kernel<<<(M_ * 2 * H_ * 16) / 256, 256>>>(qkv);

    // 3) Flash attention
    const int smem_bytes = FLASH_SMEM_FLOATS * sizeof(float);
    cudaFuncSetAttribute(flash_attn, cudaFuncAttributeMaxDynamicSharedMemorySize,
                         smem_bytes);
    dim3 g3(S_ / QT, B_ * H_);
    flash_attn<<<g3, 256, smem_bytes>>>(qkv, attn);

    // 4) Output projection: [4096,1024] @ [1024,1024]^T + bias
    dim3 g4(1024 / 128, 4096 / 128);
    sgemm_nt_bias<<<g4, 256>>>(attn, Wout, bout, out, M_, DM_, DM_);
}

// round 3
// speedup vs baseline: 1.2500x; 1.2500x over previous
#include <cuda_runtime.h>
#include <cuda_bf16.h>
#include <math.h>
#include <stdint.h>

// Problem constants
#define B_   2
#define S_   2048
#define DM_  1024
#define H_   16
#define DH_  64
#define M_   (B_ * S_)          // 4096 rows
#define ROWSTRIDE 3072          // qkv row stride (3*DM_)

// Scratch (allocation-free rule: __device__ globals)
__device__ float g_qkv[(size_t)M_ * 3 * DM_];   // [4096][3][16][64]
__device__ float g_attn[(size_t)M_ * DM_];      // [B,S,Dm] attention output
__device__ __nv_bfloat16 g_xh[(size_t)M_ * DM_];
__device__ __nv_bfloat16 g_xl[(size_t)M_ * DM_];
__device__ __nv_bfloat16 g_wqh[(size_t)3 * DM_ * DM_];
__device__ __nv_bfloat16 g_wql[(size_t)3 * DM_ * DM_];
__device__ __nv_bfloat16 g_woh[(size_t)DM_ * DM_];
__device__ __nv_bfloat16 g_wol[(size_t)DM_ * DM_];
__device__ __nv_bfloat16 g_ah[(size_t)M_ * DM_];
__device__ __nv_bfloat16 g_al[(size_t)M_ * DM_];

// ---------------------------------------------------------------------------
// mma.sync helpers (sm_80-era PTX: assembles for plain sm_103 target)
// ---------------------------------------------------------------------------
__device__ __forceinline__ uint32_t smem_u32(const void* p) {
    uint32_t a;
    asm("{ .reg .u64 t; cvta.to.shared.u64 t, %1; cvt.u32.u64 %0, t; }"
        : "=r"(a) : "l"(p));
    return a;
}

#define LDSM_X4(r0, r1, r2, r3, addr) \
    asm volatile("ldmatrix.sync.aligned.m8n8.x4.shared.b16 {%0,%1,%2,%3}, [%4];" \
                 : "=r"(r0), "=r"(r1), "=r"(r2), "=r"(r3) : "r"(addr))
#define LDSM_X2(r0, r1, addr) \
    asm volatile("ldmatrix.sync.aligned.m8n8.x2.shared.b16 {%0,%1}, [%2];" \
                 : "=r"(r0), "=r"(r1) : "r"(addr))

__device__ __forceinline__ void mma16816(float* c, const uint32_t* a,
                                         const uint32_t* b) {
    asm volatile(
        "mma.sync.aligned.m16n8k16.row.col.f32.bf16.bf16.f32 "
        "{%0,%1,%2,%3}, {%4,%5,%6,%7}, {%8,%9}, {%0,%1,%2,%3};"
        : "+f"(c[0]), "+f"(c[1]), "+f"(c[2]), "+f"(c[3])
        : "r"(a[0]), "r"(a[1]), "r"(a[2]), "r"(a[3]), "r"(b[0]), "r"(b[1]));
}

// ---------------------------------------------------------------------------
// split: fp32 -> bf16 hi + bf16 lo (hi = rn(x), lo = rn(x - hi))
// ---------------------------------------------------------------------------
__global__ __launch_bounds__(256) void split_bf16(
    const float* __restrict__ src, __nv_bfloat16* __restrict__ hi,
    __nv_bfloat16* __restrict__ lo, int n4)
{
    int i = blockIdx.x * blockDim.x + threadIdx.x;
    if (i >= n4) return;
    float4 v = ((const float4*)src)[i];
    __nv_bfloat16 h0 = __float2bfloat16(v.x);
    __nv_bfloat16 h1 = __float2bfloat16(v.y);
    __nv_bfloat16 h2 = __float2bfloat16(v.z);
    __nv_bfloat16 h3 = __float2bfloat16(v.w);
    __nv_bfloat16 l0 = __float2bfloat16(v.x - __bfloat162float(h0));
    __nv_bfloat16 l1 = __float2bfloat16(v.y - __bfloat162float(h1));
    __nv_bfloat16 l2 = __float2bfloat16(v.z - __bfloat162float(h2));
    __nv_bfloat16 l3 = __float2bfloat16(v.w - __bfloat162float(h3));
    __nv_bfloat162 hh0; hh0.x = h0; hh0.y = h1;
    __nv_bfloat162 hh1; hh1.x = h2; hh1.y = h3;
    __nv_bfloat162 ll0; ll0.x = l0; ll0.y = l1;
    __nv_bfloat162 ll1; ll1.x = l2; ll1.y = l3;
    uint2 hp, lp;
    hp.x = *(uint32_t*)&hh0; hp.y = *(uint32_t*)&hh1;
    lp.x = *(uint32_t*)&ll0; lp.y = *(uint32_t*)&ll1;
    ((uint2*)hi)[i] = hp;
    ((uint2*)lo)[i] = lp;
}

// ---------------------------------------------------------------------------
// HMMA GEMM: C[M,N] = A[M,K] @ W[N,K]^T + bias, split-bf16 3-pass.
// 128x128 CTA tile, BK=32, 8 warps (2 M x 4 N), warp tile 64x32.
// ---------------------------------------------------------------------------
#define BK 32
#define ASTR 40   // smem stride in halfs (32 + 8 pad)

__global__ __launch_bounds__(256) void gemm_mma_bf16x3(
    const __nv_bfloat16* __restrict__ Ah, const __nv_bfloat16* __restrict__ Al,
    const __nv_bfloat16* __restrict__ Bh, const __nv_bfloat16* __restrict__ Bl,
    const float* __restrict__ bias, float* __restrict__ C,
    int M, int N, int K)
{
    __shared__ __nv_bfloat16 sAh[128 * ASTR];
    __shared__ __nv_bfloat16 sAl[128 * ASTR];
    __shared__ __nv_bfloat16 sBh[128 * ASTR];
    __shared__ __nv_bfloat16 sBl[128 * ASTR];

    const int tid = threadIdx.x;
    const int wid = tid >> 5;
    const int lane = tid & 31;
    const int warp_m = wid & 1;          // 2 warps in M
    const int warp_n = wid >> 1;         // 4 warps in N
    const int bm = blockIdx.y * 128;
    const int bn = blockIdx.x * 128;

    const __nv_bfloat16* aH = Ah + (size_t)bm * K;
    const __nv_bfloat16* aL = Al + (size_t)bm * K;
    const __nv_bfloat16* bH = Bh + (size_t)bn * K;
    const __nv_bfloat16* bL = Bl + (size_t)bn * K;

    float acc[4][4][4];
#pragma unroll
    for (int i = 0; i < 4; i++)
#pragma unroll
        for (int j = 0; j < 4; j++)
#pragma unroll
            for (int e = 0; e < 4; e++) acc[i][j][e] = 0.f;

    const uint32_t uAh = smem_u32(sAh), uAl = smem_u32(sAl);
    const uint32_t uBh = smem_u32(sBh), uBl = smem_u32(sBl);

    for (int k0 = 0; k0 < K; k0 += BK) {
        // Load tiles: 128 rows x 32 halfs per tile, uint4 = 8 halfs
#pragma unroll
        for (int i = 0; i < 2; i++) {
            int L = i * 256 + tid;           // 0..511
            int row = L >> 2;
            int c8 = (L & 3) * 8;
            size_t g = (size_t)row * K + k0 + c8;
            int so = row * ASTR + c8;
            *(uint4*)(sAh + so) = *(const uint4*)(aH + g);
            *(uint4*)(sAl + so) = *(const uint4*)(aL + g);
            *(uint4*)(sBh + so) = *(const uint4*)(bH + g);
            *(uint4*)(sBl + so) = *(const uint4*)(bL + g);
        }
        __syncthreads();

#pragma unroll
        for (int ks = 0; ks < 2; ks++) {
            uint32_t ah[4][4], al[4][4], bh[4][2], bl[4][2];
            const int kof = ks * 16 + (lane >> 4) * 8;   // A k-offset
            const int kofb = ks * 16 + ((lane >> 3) & 1) * 8;
#pragma unroll
            for (int mi = 0; mi < 4; mi++) {
                int r = (warp_m * 64 + mi * 16 + (lane & 15)) * ASTR + kof;
                LDSM_X4(ah[mi][0], ah[mi][1], ah[mi][2], ah[mi][3],
                        uAh + (uint32_t)r * 2);
                LDSM_X4(al[mi][0], al[mi][1], al[mi][2], al[mi][3],
                        uAl + (uint32_t)r * 2);
            }
#pragma unroll
            for (int ni = 0; ni < 4; ni++) {
                int r = (warp_n * 32 + ni * 8 + (lane & 7)) * ASTR + kofb;
                LDSM_X2(bh[ni][0], bh[ni][1], uBh + (uint32_t)r * 2);
                LDSM_X2(bl[ni][0], bl[ni][1], uBl + (uint32_t)r * 2);
            }
#pragma unroll
            for (int mi = 0; mi < 4; mi++)
#pragma unroll
                for (int ni = 0; ni < 4; ni++) {
                    mma16816(acc[mi][ni], ah[mi], bh[ni]);
                    mma16816(acc[mi][ni], ah[mi], bl[ni]);
                    mma16816(acc[mi][ni], al[mi], bh[ni]);
                }
        }
        __syncthreads();
    }

    // Epilogue: acc layout per mma: c0/c1 = (row, col), (row, col+1);
    // c2/c3 = (row+8, col..col+1); row = lane/4, col = 2*(lane%4)
    const int m0 = bm + warp_m * 64;
    const int n0 = bn + warp_n * 32;
#pragma unroll
    for (int mi = 0; mi < 4; mi++) {
#pragma unroll
        for (int ni = 0; ni < 4; ni++) {
            int col = n0 + ni * 8 + (lane & 3) * 2;
            float2 bv = *(const float2*)(bias + col);
            int r0 = m0 + mi * 16 + (lane >> 2);
            float2 o0, o1;
            o0.x = acc[mi][ni][0] + bv.x;
            o0.y = acc[mi][ni][1] + bv.y;
            o1.x = acc[mi][ni][2] + bv.x;
            o1.y = acc[mi][ni][3] + bv.y;
            *(float2*)(C + (size_t)r0 * N + col) = o0;
            *(float2*)(C + (size_t)(r0 + 8) * N + col) = o1;
        }
    }
}

// ---------------------------------------------------------------------------
// Partial RoPE, in-place on q and k slices of g_qkv. (unchanged)
// ---------------------------------------------------------------------------
__global__ __launch_bounds__(256) void rope_kernel(float* __restrict__ qkv)
{
    int tid = blockIdx.x * blockDim.x + threadIdx.x;
    if (tid >= M_ * 2 * H_ * 16) return;
    int pair = tid & 15;
    int h    = (tid >> 4) & 15;
    int qk   = (tid >> 8) & 1;
    int row  = tid >> 9;
    int s    = row & (S_ - 1);

    float inv_freq = (float)pow(10000.0, -(double)pair / 16.0);
    float ang = (float)s * inv_freq;
    float sn, cs;
    sincosf(ang, &sn, &cs);

    float* p = qkv + (size_t)row * ROWSTRIDE + qk * DM_ + h * DH_ + 2 * pair;
    float x1 = p[0], x2 = p[1];
    p[0] = x1 * cs - x2 * sn;
    p[1] = x2 * cs + x1 * sn;
}

// ---------------------------------------------------------------------------
// Flash attention (fp32, unchanged from round 1)
// ---------------------------------------------------------------------------
#define QT 128
#define KT 64
#define QSTRIDE 132
#define KSTRIDE 68
#define FLASH_SMEM_FLOATS (64*QSTRIDE + 64*KSTRIDE + 64*KSTRIDE + 128*KSTRIDE)

__global__ __launch_bounds__(256) void flash_attn(
    const float* __restrict__ qkv, float* __restrict__ outp)
{
    extern __shared__ float sm[];
    float* Qts = sm;
    float* Kts = Qts + 64 * QSTRIDE;
    float* Vs  = Kts + 64 * KSTRIDE;
    float* Ps  = Vs  + 64 * KSTRIDE;

    const int tid = threadIdx.x;
    const int tx = tid & 15, ty = tid >> 4;
    const int bh = blockIdx.y;
    const int bb = bh >> 4, h = bh & 15;
    const int q0 = blockIdx.x * QT;

    const float* qbase = qkv + (size_t)bb * S_ * ROWSTRIDE + h * DH_;
    const float* kbase = qbase + DM_;
    const float* vbase = qbase + 2 * DM_;

#pragma unroll
    for (int i = 0; i < 8; i++) {
        int L = i * 256 + tid;
        int row = L >> 4;
        int d4 = (L & 15) << 2;
        float4 v = *(const float4*)(qbase + (size_t)(q0 + row) * ROWSTRIDE + d4);
        Qts[(d4 + 0) * QSTRIDE + row] = v.x;
        Qts[(d4 + 1) * QSTRIDE + row] = v.y;
        Qts[(d4 + 2) * QSTRIDE + row] = v.z;
        Qts[(d4 + 3) * QSTRIDE + row] = v.w;
    }

    float mrow[2][4], lrow[2][4], acc[2][4][4];
#pragma unroll
    for (int g = 0; g < 2; g++)
#pragma unroll
        for (int a = 0; a < 4; a++) {
            mrow[g][a] = -INFINITY;
            lrow[g][a] = 0.f;
#pragma unroll
            for (int j = 0; j < 4; j++) acc[g][a][j] = 0.f;
        }

    const float scale = 0.125f;

    for (int t = 0; t < S_ / KT; t++) {
#pragma unroll
        for (int i = 0; i < 4; i++) {
            int L = i * 256 + tid;
            int row = L >> 4;
            int d4 = (L & 15) << 2;
            const size_t goff = (size_t)(t * KT + row) * ROWSTRIDE + d4;
            float4 kv = *(const float4*)(kbase + goff);
            Kts[(d4 + 0) * KSTRIDE + row] = kv.x;
            Kts[(d4 + 1) * KSTRIDE + row] = kv.y;
            Kts[(d4 + 2) * KSTRIDE + row] = kv.z;
            Kts[(d4 + 3) * KSTRIDE + row] = kv.w;
            float4 vv = *(const float4*)(vbase + goff);
            *(float4*)&Vs[row * KSTRIDE + d4] = vv;
        }
        __syncthreads();

        float s[2][4][4];
#pragma unroll
        for (int g = 0; g < 2; g++)
#pragma unroll
            for (int a = 0; a < 4; a++)
#pragma unroll
                for (int j = 0; j < 4; j++) s[g][a][j] = 0.f;

#pragma unroll 8
        for (int k = 0; k < 64; k++) {
            float qa[4], qb[4], kk[4];
            *(float4*)qa = *(const float4*)&Qts[k * QSTRIDE + 4 * ty];
            *(float4*)qb = *(const float4*)&Qts[k * QSTRIDE + 64 + 4 * ty];
            *(float4*)kk = *(const float4*)&Kts[k * KSTRIDE + 4 * tx];
#pragma unroll
            for (int a = 0; a < 4; a++)
#pragma unroll
                for (int j = 0; j < 4; j++) {
                    s[0][a][j] = fmaf(qa[a], kk[j], s[0][a][j]);
                    s[1][a][j] = fmaf(qb[a], kk[j], s[1][a][j]);
                }
        }

#pragma unroll
        for (int g = 0; g < 2; g++)
#pragma unroll
            for (int a = 0; a < 4; a++) {
                float rm = fmaxf(fmaxf(s[g][a][0], s[g][a][1]),
                                 fmaxf(s[g][a][2], s[g][a][3]));
#pragma unroll
                for (int off = 8; off >= 1; off >>= 1)
                    rm = fmaxf(rm, __shfl_xor_sync(0xffffffffu, rm, off));
                float mnew = fmaxf(mrow[g][a], rm * scale);
                float corr = __expf(mrow[g][a] - mnew);
                float rowsum = 0.f;
                float4 p4;
                p4.x = __expf(fmaf(s[g][a][0], scale, -mnew));
                p4.y = __expf(fmaf(s[g][a][1], scale, -mnew));
                p4.z = __expf(fmaf(s[g][a][2], scale, -mnew));
                p4.w = __expf(fmaf(s[g][a][3], scale, -mnew));
                rowsum = p4.x + p4.y + p4.z + p4.w;
#pragma unroll
                for (int off = 8; off >= 1; off >>= 1)
                    rowsum += __shfl_xor_sync(0xffffffffu, rowsum, off);
                lrow[g][a] = lrow[g][a] * corr + rowsum;
                mrow[g][a] = mnew;
#pragma unroll
                for (int j = 0; j < 4; j++) acc[g][a][j] *= corr;
                int r = 64 * g + 4 * ty + a;
                *(float4*)&Ps[r * KSTRIDE + 4 * tx] = p4;
            }
        __syncthreads();

#pragma unroll 2
        for (int j = 0; j < 64; j += 4) {
            float4 v0 = *(const float4*)&Vs[(j + 0) * KSTRIDE + 4 * tx];
            float4 v1 = *(const float4*)&Vs[(j + 1) * KSTRIDE + 4 * tx];
            float4 v2 = *(const float4*)&Vs[(j + 2) * KSTRIDE + 4 * tx];
            float4 v3 = *(const float4*)&Vs[(j + 3) * KSTRIDE + 4 * tx];
#pragma unroll
            for (int g = 0; g < 2; g++)
#pragma unroll
                for (int a = 0; a < 4; a++) {
                    int r = 64 * g + 4 * ty + a;
                    float4 p4 = *(const float4*)&Ps[r * KSTRIDE + j];
                    acc[g][a][0] = fmaf(p4.x, v0.x, acc[g][a][0]);
                    acc[g][a][1] = fmaf(p4.x, v0.y, acc[g][a][1]);
                    acc[g][a][2] = fmaf(p4.x, v0.z, acc[g][a][2]);
                    acc[g][a][3] = fmaf(p4.x, v0.w, acc[g][a][3]);
                    acc[g][a][0] = fmaf(p4.y, v1.x, acc[g][a][0]);
                    acc[g][a][1] = fmaf(p4.y, v1.y, acc[g][a][1]);
                    acc[g][a][2] = fmaf(p4.y, v1.z, acc[g][a][2]);
                    acc[g][a][3] = fmaf(p4.y, v1.w, acc[g][a][3]);
                    acc[g][a][0] = fmaf(p4.z, v2.x, acc[g][a][0]);
                    acc[g][a][1] = fmaf(p4.z, v2.y, acc[g][a][1]);
                    acc[g][a][2] = fmaf(p4.z, v2.z, acc[g][a][2]);
                    acc[g][a][3] = fmaf(p4.z, v2.w, acc[g][a][3]);
                    acc[g][a][0] = fmaf(p4.w, v3.x, acc[g][a][0]);
                    acc[g][a][1] = fmaf(p4.w, v3.y, acc[g][a][1]);
                    acc[g][a][2] = fmaf(p4.w, v3.z, acc[g][a][2]);
                    acc[g][a][3] = fmaf(p4.w, v3.w, acc[g][a][3]);
                }
        }
        __syncthreads();
    }

#pragma unroll
    for (int g = 0; g < 2; g++)
#pragma unroll
        for (int a = 0; a < 4; a++) {
            float inv = 1.f / lrow[g][a];
            int r = q0 + 64 * g + 4 * ty + a;
            float4 o;
            o.x = acc[g][a][0] * inv;
            o.y = acc[g][a][1] * inv;
            o.z = acc[g][a][2] * inv;
            o.w = acc[g][a][3] * inv;
            *(float4*)(outp + ((size_t)bb * S_ + r) * DM_ + h * DH_ + 4 * tx) = o;
        }
}

// ---------------------------------------------------------------------------
extern "C" void kernel_launch(void* const* d_in, const int* in_sizes, int n_in,
                              void* d_out, int out_size)
{
    const float* x    = (const float*)d_in[0];
    const float* Wqkv = (const float*)d_in[1];
    const float* bqkv = (const float*)d_in[2];
    const float* Wout = (const float*)d_in[3];
    const float* bout = (const float*)d_in[4];
    float* out = (float*)d_out;

    float *qkv = nullptr, *attn = nullptr;
    __nv_bfloat16 *xh, *xl, *wqh, *wql, *woh, *wol, *ah, *al;
    cudaGetSymbolAddress((void**)&qkv, g_qkv);
    cudaGetSymbolAddress((void**)&attn, g_attn);
    cudaGetSymbolAddress((void**)&xh, g_xh);
    cudaGetSymbolAddress((void**)&xl, g_xl);
    cudaGetSymbolAddress((void**)&wqh, g_wqh);
    cudaGetSymbolAddress((void**)&wql, g_wql);
    cudaGetSymbolAddress((void**)&woh, g_woh);
    cudaGetSymbolAddress((void**)&wol, g_wol);
    cudaGetSymbolAddress((void**)&ah, g_ah);
    cudaGetSymbolAddress((void**)&al, g_al);

    const int flash_smem = FLASH_SMEM_FLOATS * sizeof(float);
    cudaFuncSetAttribute(flash_attn, cudaFuncAttributeMaxDynamicSharedMemorySize,
                         flash_smem);

    // 0) split inputs to bf16 hi/lo
    split_bf16<<<(M_ * DM_ / 4 + 255) / 256, 256>>>(x, xh, xl, M_ * DM_ / 4);
    split_bf16<<<(3 * DM_ * DM_ / 4 + 255) / 256, 256>>>(Wqkv, wqh, wql,
                                                         3 * DM_ * DM_ / 4);
    split_bf16<<<(DM_ * DM_ / 4 + 255) / 256, 256>>>(Wout, woh, wol,
                                                     DM_ * DM_ / 4);

    // 1) QKV projection (HMMA): [4096,3072] = x @ Wqkv^T + b
    dim3 g1(3 * DM_ / 128, M_ / 128);
    gemm_mma_bf16x3<<<g1, 256>>>(xh, xl, wqh, wql, bqkv, qkv, M_, 3 * DM_, DM_);

    // 2) RoPE on q,k (in place)
    rope_kernel<<<(M_ * 2 * H_ * 16) / 256, 256>>>(qkv);

    // 3) Flash attention (fp32)
    dim3 g3(S_ / QT, B_ * H_);
    flash_attn<<<g3, 256, flash_smem>>>(qkv, attn);

    // 4) split attention output, then out projection (HMMA)
    split_bf16<<<(M_ * DM_ / 4 + 255) / 256, 256>>>(attn, ah, al, M_ * DM_ / 4);
    dim3 g4(DM_ / 128, M_ / 128);
    gemm_mma_bf16x3<<<g4, 256>>>(ah, al, woh, wol, bout, out, M_, DM_, DM_);
}

// round 4
// speedup vs baseline: 1.5013x; 1.2011x over previous
#include <cuda_runtime.h>
#include <cuda_bf16.h>
#include <math.h>
#include <stdint.h>

// Problem constants
#define B_   2
#define S_   2048
#define DM_  1024
#define H_   16
#define DH_  64
#define M_   (B_ * S_)          // 4096 rows
#define ROWSTRIDE 3072          // qkv row stride (3*DM_)

// Scratch (allocation-free rule: __device__ globals)
__device__ float g_qkv[(size_t)M_ * 3 * DM_];
__device__ float g_attn[(size_t)M_ * DM_];
__device__ __nv_bfloat16 g_qkvh[(size_t)M_ * 3 * DM_];
__device__ __nv_bfloat16 g_qkvl[(size_t)M_ * 3 * DM_];
__device__ __nv_bfloat16 g_xh[(size_t)M_ * DM_];
__device__ __nv_bfloat16 g_xl[(size_t)M_ * DM_];
__device__ __nv_bfloat16 g_wqh[(size_t)3 * DM_ * DM_];
__device__ __nv_bfloat16 g_wql[(size_t)3 * DM_ * DM_];
__device__ __nv_bfloat16 g_woh[(size_t)DM_ * DM_];
__device__ __nv_bfloat16 g_wol[(size_t)DM_ * DM_];
__device__ __nv_bfloat16 g_ah[(size_t)M_ * DM_];
__device__ __nv_bfloat16 g_al[(size_t)M_ * DM_];

// ---------------------------------------------------------------------------
// mma.sync helpers (sm_80-era PTX)
// ---------------------------------------------------------------------------
__device__ __forceinline__ uint32_t smem_u32(const void* p) {
    uint32_t a;
    asm("{ .reg .u64 t; cvta.to.shared.u64 t, %1; cvt.u32.u64 %0, t; }"
        : "=r"(a) : "l"(p));
    return a;
}

#define LDSM_X4(r0, r1, r2, r3, addr) \
    asm volatile("ldmatrix.sync.aligned.m8n8.x4.shared.b16 {%0,%1,%2,%3}, [%4];" \
                 : "=r"(r0), "=r"(r1), "=r"(r2), "=r"(r3) : "r"(addr))
#define LDSM_X2(r0, r1, addr) \
    asm volatile("ldmatrix.sync.aligned.m8n8.x2.shared.b16 {%0,%1}, [%2];" \
                 : "=r"(r0), "=r"(r1) : "r"(addr))
#define LDSM_X2T(r0, r1, addr) \
    asm volatile("ldmatrix.sync.aligned.m8n8.x2.trans.shared.b16 {%0,%1}, [%2];" \
                 : "=r"(r0), "=r"(r1) : "r"(addr))

__device__ __forceinline__ void mma16816(float* c, const uint32_t* a,
                                         const uint32_t* b) {
    asm volatile(
        "mma.sync.aligned.m16n8k16.row.col.f32.bf16.bf16.f32 "
        "{%0,%1,%2,%3}, {%4,%5,%6,%7}, {%8,%9}, {%0,%1,%2,%3};"
        : "+f"(c[0]), "+f"(c[1]), "+f"(c[2]), "+f"(c[3])
        : "r"(a[0]), "r"(a[1]), "r"(a[2]), "r"(a[3]), "r"(b[0]), "r"(b[1]));
}

// ---------------------------------------------------------------------------
// split: fp32 -> bf16 hi + bf16 lo
// ---------------------------------------------------------------------------
__global__ __launch_bounds__(256) void split_bf16(
    const float* __restrict__ src, __nv_bfloat16* __restrict__ hi,
    __nv_bfloat16* __restrict__ lo, int n4)
{
    int i = blockIdx.x * blockDim.x + threadIdx.x;
    if (i >= n4) return;
    float4 v = ((const float4*)src)[i];
    __nv_bfloat162 h0 = __float22bfloat162_rn(make_float2(v.x, v.y));
    __nv_bfloat162 h1 = __float22bfloat162_rn(make_float2(v.z, v.w));
    float2 b0 = __bfloat1622float2(h0);
    float2 b1 = __bfloat1622float2(h1);
    __nv_bfloat162 l0 = __float22bfloat162_rn(make_float2(v.x - b0.x, v.y - b0.y));
    __nv_bfloat162 l1 = __float22bfloat162_rn(make_float2(v.z - b1.x, v.w - b1.y));
    uint2 hp, lp;
    hp.x = *(uint32_t*)&h0; hp.y = *(uint32_t*)&h1;
    lp.x = *(uint32_t*)&l0; lp.y = *(uint32_t*)&l1;
    ((uint2*)hi)[i] = hp;
    ((uint2*)lo)[i] = lp;
}

// ---------------------------------------------------------------------------
// HMMA GEMM: C[M,N] = A[M,K] @ W[N,K]^T + bias, split-bf16 3-pass. (round 3)
// ---------------------------------------------------------------------------
#define BK 32
#define ASTR 40

__global__ __launch_bounds__(256) void gemm_mma_bf16x3(
    const __nv_bfloat16* __restrict__ Ah, const __nv_bfloat16* __restrict__ Al,
    const __nv_bfloat16* __restrict__ Bh, const __nv_bfloat16* __restrict__ Bl,
    const float* __restrict__ bias, float* __restrict__ C,
    int M, int N, int K)
{
    __shared__ __nv_bfloat16 sAh[128 * ASTR];
    __shared__ __nv_bfloat16 sAl[128 * ASTR];
    __shared__ __nv_bfloat16 sBh[128 * ASTR];
    __shared__ __nv_bfloat16 sBl[128 * ASTR];

    const int tid = threadIdx.x;
    const int wid = tid >> 5;
    const int lane = tid & 31;
    const int warp_m = wid & 1;
    const int warp_n = wid >> 1;
    const int bm = blockIdx.y * 128;
    const int bn = blockIdx.x * 128;

    const __nv_bfloat16* aH = Ah + (size_t)bm * K;
    const __nv_bfloat16* aL = Al + (size_t)bm * K;
    const __nv_bfloat16* bH = Bh + (size_t)bn * K;
    const __nv_bfloat16* bL = Bl + (size_t)bn * K;

    float acc[4][4][4];
#pragma unroll
    for (int i = 0; i < 4; i++)
#pragma unroll
        for (int j = 0; j < 4; j++)
#pragma unroll
            for (int e = 0; e < 4; e++) acc[i][j][e] = 0.f;

    const uint32_t uAh = smem_u32(sAh), uAl = smem_u32(sAl);
    const uint32_t uBh = smem_u32(sBh), uBl = smem_u32(sBl);

    for (int k0 = 0; k0 < K; k0 += BK) {
#pragma unroll
        for (int i = 0; i < 2; i++) {
            int L = i * 256 + tid;
            int row = L >> 2;
            int c8 = (L & 3) * 8;
            size_t g = (size_t)row * K + k0 + c8;
            int so = row * ASTR + c8;
            *(uint4*)(sAh + so) = *(const uint4*)(aH + g);
            *(uint4*)(sAl + so) = *(const uint4*)(aL + g);
            *(uint4*)(sBh + so) = *(const uint4*)(bH + g);
            *(uint4*)(sBl + so) = *(const uint4*)(bL + g);
        }
        __syncthreads();

#pragma unroll
        for (int ks = 0; ks < 2; ks++) {
            uint32_t ah[4][4], al[4][4], bh[4][2], bl[4][2];
            const int kof = ks * 16 + (lane >> 4) * 8;
            const int kofb = ks * 16 + ((lane >> 3) & 1) * 8;
#pragma unroll
            for (int mi = 0; mi < 4; mi++) {
                int r = (warp_m * 64 + mi * 16 + (lane & 15)) * ASTR + kof;
                LDSM_X4(ah[mi][0], ah[mi][1], ah[mi][2], ah[mi][3],
                        uAh + (uint32_t)r * 2);
                LDSM_X4(al[mi][0], al[mi][1], al[mi][2], al[mi][3],
                        uAl + (uint32_t)r * 2);
            }
#pragma unroll
            for (int ni = 0; ni < 4; ni++) {
                int r = (warp_n * 32 + ni * 8 + (lane & 7)) * ASTR + kofb;
                LDSM_X2(bh[ni][0], bh[ni][1], uBh + (uint32_t)r * 2);
                LDSM_X2(bl[ni][0], bl[ni][1], uBl + (uint32_t)r * 2);
            }
#pragma unroll
            for (int mi = 0; mi < 4; mi++)
#pragma unroll
                for (int ni = 0; ni < 4; ni++) {
                    mma16816(acc[mi][ni], ah[mi], bh[ni]);
                    mma16816(acc[mi][ni], ah[mi], bl[ni]);
                    mma16816(acc[mi][ni], al[mi], bh[ni]);
                }
        }
        __syncthreads();
    }

    const int m0 = bm + warp_m * 64;
    const int n0 = bn + warp_n * 32;
#pragma unroll
    for (int mi = 0; mi < 4; mi++) {
#pragma unroll
        for (int ni = 0; ni < 4; ni++) {
            int col = n0 + ni * 8 + (lane & 3) * 2;
            float2 bv = *(const float2*)(bias + col);
            int r0 = m0 + mi * 16 + (lane >> 2);
            float2 o0, o1;
            o0.x = acc[mi][ni][0] + bv.x;
            o0.y = acc[mi][ni][1] + bv.y;
            o1.x = acc[mi][ni][2] + bv.x;
            o1.y = acc[mi][ni][3] + bv.y;
            *(float2*)(C + (size_t)r0 * N + col) = o0;
            *(float2*)(C + (size_t)(r0 + 8) * N + col) = o1;
        }
    }
}

// ---------------------------------------------------------------------------
// RoPE + hi/lo split of the whole qkv tensor (fp32 -> bf16 hi/lo, rope on q,k)
// One thread per interleaved pair.
// ---------------------------------------------------------------------------
__global__ __launch_bounds__(256) void rope_split(
    const float* __restrict__ qkv, __nv_bfloat16* __restrict__ oh,
    __nv_bfloat16* __restrict__ ol)
{
    int idx = blockIdx.x * blockDim.x + threadIdx.x;
    if (idx >= M_ * (ROWSTRIDE / 2)) return;
    int row = idx / (ROWSTRIDE / 2);
    int col = (idx % (ROWSTRIDE / 2)) * 2;
    float2 v = *(const float2*)(qkv + (size_t)row * ROWSTRIDE + col);
    int sec = col >> 10;                 // 0=q 1=k 2=v
    int p = (col & 63) >> 1;             // pair index within head (0..31)
    if (sec < 2 && p < 16) {
        int s = row & (S_ - 1);
        float inv_freq = (float)pow(10000.0, -(double)p / 16.0);
        float sn, cs;
        sincosf((float)s * inv_freq, &sn, &cs);
        float x1 = v.x, x2 = v.y;
        v.x = x1 * cs - x2 * sn;
        v.y = x2 * cs + x1 * sn;
    }
    __nv_bfloat162 hh = __float22bfloat162_rn(v);
    float2 back = __bfloat1622float2(hh);
    __nv_bfloat162 ll = __float22bfloat162_rn(make_float2(v.x - back.x, v.y - back.y));
    *(__nv_bfloat162*)(oh + (size_t)row * ROWSTRIDE + col) = hh;
    *(__nv_bfloat162*)(ol + (size_t)row * ROWSTRIDE + col) = ll;
}

// ---------------------------------------------------------------------------
// Flash attention via HMMA, split-bf16 3-pass on both matmuls.
// Per CTA: one (b,h), 128 queries. 8 warps x 16 rows. KV tiles of 64.
// ---------------------------------------------------------------------------
#define FST 72   // smem row stride in halfs
#define FLASH_SMEM_BYTES (512 * FST * 2)   // (128*2 + 64*4) rows = 512

__device__ __forceinline__ uint32_t packbf(float a, float b) {
    __nv_bfloat162 t = __float22bfloat162_rn(make_float2(a, b));
    return *(uint32_t*)&t;
}

__global__ __launch_bounds__(256, 2) void flash_mma(
    const __nv_bfloat16* __restrict__ qkvh,
    const __nv_bfloat16* __restrict__ qkvl,
    float* __restrict__ outp)
{
    extern __shared__ __nv_bfloat16 fsm[];
    __nv_bfloat16* sQh = fsm;                 // [128][FST]
    __nv_bfloat16* sQl = fsm + 128 * FST;     // [128][FST]
    __nv_bfloat16* sKh = fsm + 256 * FST;     // [64][FST]
    __nv_bfloat16* sKl = fsm + 320 * FST;
    __nv_bfloat16* sVh = fsm + 384 * FST;
    __nv_bfloat16* sVl = fsm + 448 * FST;

    const int tid = threadIdx.x;
    const int wid = tid >> 5, lane = tid & 31;
    const int bh = blockIdx.y;
    const int bb = bh >> 4, h = bh & 15;
    const int q0 = blockIdx.x * 128;

    const size_t rowbase = (size_t)bb * S_ * ROWSTRIDE;
    const __nv_bfloat16* qbh = qkvh + rowbase + h * DH_;
    const __nv_bfloat16* qbl = qkvl + rowbase + h * DH_;

    // Load Q tile (128 x 64 halfs, hi & lo)
#pragma unroll
    for (int it = 0; it < 4; it++) {
        int L = it * 256 + tid;          // 0..1023
        int row = L >> 3, c8 = (L & 7) * 8;
        size_t g = (size_t)(q0 + row) * ROWSTRIDE + c8;
        *(uint4*)(sQh + row * FST + c8) = *(const uint4*)(qbh + g);
        *(uint4*)(sQl + row * FST + c8) = *(const uint4*)(qbl + g);
    }

    float o[8][4];
#pragma unroll
    for (int ni = 0; ni < 8; ni++)
#pragma unroll
        for (int e = 0; e < 4; e++) o[ni][e] = 0.f;
    float m0 = -INFINITY, m1 = -INFINITY, l0 = 0.f, l1 = 0.f;

    const uint32_t uQh = smem_u32(sQh), uQl = smem_u32(sQl);
    const uint32_t uKh = smem_u32(sKh), uKl = smem_u32(sKl);
    const uint32_t uVh = smem_u32(sVh), uVl = smem_u32(sVl);

    const uint32_t qrow = wid * 16 + (lane & 15);
    const uint32_t qcol = 8 * (lane >> 4);
    const float scale = 0.125f;

    for (int t = 0; t < S_ / 64; t++) {
        __syncthreads();
        // Load K/V tiles (hi & lo)
#pragma unroll
        for (int it = 0; it < 8; it++) {
            int L = it * 256 + tid;      // 0..2047
            int tsel = L >> 9;
            int r = (L >> 3) & 63, c8 = (L & 7) * 8;
            size_t g = (size_t)(t * 64 + r) * ROWSTRIDE + c8;
            const __nv_bfloat16* src =
                (tsel == 0) ? qbh + DM_ : (tsel == 1) ? qbl + DM_ :
                (tsel == 2) ? qbh + 2 * DM_ : qbl + 2 * DM_;
            __nv_bfloat16* dst =
                (tsel == 0) ? sKh : (tsel == 1) ? sKl :
                (tsel == 2) ? sVh : sVl;
            *(uint4*)(dst + r * FST + c8) = *(const uint4*)(src + g);
        }
        __syncthreads();

        // S = Q @ K^T (3-pass)
        float s[8][4];
#pragma unroll
        for (int ni = 0; ni < 8; ni++)
#pragma unroll
            for (int e = 0; e < 4; e++) s[ni][e] = 0.f;

#pragma unroll
        for (int kc = 0; kc < 4; kc++) {
            uint32_t qh4[4], ql4[4];
            uint32_t qa = (qrow * FST + kc * 16 + qcol) * 2;
            LDSM_X4(qh4[0], qh4[1], qh4[2], qh4[3], uQh + qa);
            LDSM_X4(ql4[0], ql4[1], ql4[2], ql4[3], uQl + qa);
#pragma unroll
            for (int ni = 0; ni < 8; ni++) {
                uint32_t kb[2], kl2[2];
                uint32_t ka = ((ni * 8 + (lane & 7)) * FST + kc * 16
                               + 8 * ((lane >> 3) & 1)) * 2;
                LDSM_X2(kb[0], kb[1], uKh + ka);
                LDSM_X2(kl2[0], kl2[1], uKl + ka);
                mma16816(s[ni], qh4, kb);
                mma16816(s[ni], qh4, kl2);
                mma16816(s[ni], ql4, kb);
            }
        }

        // Online softmax (rows r0=lane>>2, r1=r0+8; warp-local)
#pragma unroll
        for (int ni = 0; ni < 8; ni++)
#pragma unroll
            for (int e = 0; e < 4; e++) s[ni][e] *= scale;

        float rm0 = -INFINITY, rm1 = -INFINITY;
#pragma unroll
        for (int ni = 0; ni < 8; ni++) {
            rm0 = fmaxf(rm0, fmaxf(s[ni][0], s[ni][1]));
            rm1 = fmaxf(rm1, fmaxf(s[ni][2], s[ni][3]));
        }
        rm0 = fmaxf(rm0, __shfl_xor_sync(0xffffffffu, rm0, 1));
        rm0 = fmaxf(rm0, __shfl_xor_sync(0xffffffffu, rm0, 2));
        rm1 = fmaxf(rm1, __shfl_xor_sync(0xffffffffu, rm1, 1));
        rm1 = fmaxf(rm1, __shfl_xor_sync(0xffffffffu, rm1, 2));

        float mn0 = fmaxf(m0, rm0), mn1 = fmaxf(m1, rm1);
        float c0 = __expf(m0 - mn0), c1 = __expf(m1 - mn1);
        m0 = mn0; m1 = mn1;

        float rs0 = 0.f, rs1 = 0.f;
#pragma unroll
        for (int ni = 0; ni < 8; ni++) {
            s[ni][0] = __expf(s[ni][0] - mn0);
            s[ni][1] = __expf(s[ni][1] - mn0);
            s[ni][2] = __expf(s[ni][2] - mn1);
            s[ni][3] = __expf(s[ni][3] - mn1);
            rs0 += s[ni][0] + s[ni][1];
            rs1 += s[ni][2] + s[ni][3];
        }
        rs0 += __shfl_xor_sync(0xffffffffu, rs0, 1);
        rs0 += __shfl_xor_sync(0xffffffffu, rs0, 2);
        rs1 += __shfl_xor_sync(0xffffffffu, rs1, 1);
        rs1 += __shfl_xor_sync(0xffffffffu, rs1, 2);
        l0 = l0 * c0 + rs0;
        l1 = l1 * c1 + rs1;

#pragma unroll
        for (int ni = 0; ni < 8; ni++) {
            o[ni][0] *= c0; o[ni][1] *= c0;
            o[ni][2] *= c1; o[ni][3] *= c1;
        }

        // Pack P -> bf16 hi/lo A-fragments (register-only)
        uint32_t ph[8][2], pl[8][2];
#pragma unroll
        for (int ni = 0; ni < 8; ni++) {
            ph[ni][0] = packbf(s[ni][0], s[ni][1]);
            ph[ni][1] = packbf(s[ni][2], s[ni][3]);
            __nv_bfloat162 b0 = *(__nv_bfloat162*)&ph[ni][0];
            __nv_bfloat162 b1 = *(__nv_bfloat162*)&ph[ni][1];
            float2 f0 = __bfloat1622float2(b0);
            float2 f1 = __bfloat1622float2(b1);
            pl[ni][0] = packbf(s[ni][0] - f0.x, s[ni][1] - f0.y);
            pl[ni][1] = packbf(s[ni][2] - f1.x, s[ni][3] - f1.y);
        }

        // O += P @ V (3-pass)
#pragma unroll
        for (int kc = 0; kc < 4; kc++) {
            uint32_t af[4] = {ph[2 * kc][0], ph[2 * kc][1],
                              ph[2 * kc + 1][0], ph[2 * kc + 1][1]};
            uint32_t al4[4] = {pl[2 * kc][0], pl[2 * kc][1],
                               pl[2 * kc + 1][0], pl[2 * kc + 1][1]};
#pragma unroll
            for (int ni = 0; ni < 8; ni++) {
                uint32_t vb[2], vl2[2];
                uint32_t va = ((kc * 16 + (lane & 15)) * FST + ni * 8) * 2;
                LDSM_X2T(vb[0], vb[1], uVh + va);
                LDSM_X2T(vl2[0], vl2[1], uVl + va);
                mma16816(o[ni], af, vb);
                mma16816(o[ni], af, vl2);
                mma16816(o[ni], al4, vb);
            }
        }
    }

    // Epilogue
    float inv0 = 1.f / l0, inv1 = 1.f / l1;
    int r0 = q0 + wid * 16 + (lane >> 2);
    float* obase = outp + ((size_t)bb * S_ + r0) * DM_ + h * DH_;
#pragma unroll
    for (int ni = 0; ni < 8; ni++) {
        int col = ni * 8 + (lane & 3) * 2;
        float2 w0, w1;
        w0.x = o[ni][0] * inv0; w0.y = o[ni][1] * inv0;
        w1.x = o[ni][2] * inv1; w1.y = o[ni][3] * inv1;
        *(float2*)(obase + col) = w0;
        *(float2*)(obase + 8 * DM_ + col) = w1;
    }
}

// ---------------------------------------------------------------------------
extern "C" void kernel_launch(void* const* d_in, const int* in_sizes, int n_in,
                              void* d_out, int out_size)
{
    const float* x    = (const float*)d_in[0];
    const float* Wqkv = (const float*)d_in[1];
    const float* bqkv = (const float*)d_in[2];
    const float* Wout = (const float*)d_in[3];
    const float* bout = (const float*)d_in[4];
    float* out = (float*)d_out;

    float *qkv = nullptr, *attn = nullptr;
    __nv_bfloat16 *qkvh, *qkvl, *xh, *xl, *wqh, *wql, *woh, *wol, *ah, *al;
    cudaGetSymbolAddress((void**)&qkv, g_qkv);
    cudaGetSymbolAddress((void**)&attn, g_attn);
    cudaGetSymbolAddress((void**)&qkvh, g_qkvh);
    cudaGetSymbolAddress((void**)&qkvl, g_qkvl);
    cudaGetSymbolAddress((void**)&xh, g_xh);
    cudaGetSymbolAddress((void**)&xl, g_xl);
    cudaGetSymbolAddress((void**)&wqh, g_wqh);
    cudaGetSymbolAddress((void**)&wql, g_wql);
    cudaGetSymbolAddress((void**)&woh, g_woh);
    cudaGetSymbolAddress((void**)&wol, g_wol);
    cudaGetSymbolAddress((void**)&ah, g_ah);
    cudaGetSymbolAddress((void**)&al, g_al);

    cudaFuncSetAttribute(flash_mma, cudaFuncAttributeMaxDynamicSharedMemorySize,
                         FLASH_SMEM_BYTES);

    // 0) split inputs to bf16 hi/lo
    split_bf16<<<(M_ * DM_ / 4 + 255) / 256, 256>>>(x, xh, xl, M_ * DM_ / 4);
    split_bf16<<<(3 * DM_ * DM_ / 4 + 255) / 256, 256>>>(Wqkv, wqh, wql,
                                                         3 * DM_ * DM_ / 4);
    split_bf16<<<(DM_ * DM_ / 4 + 255) / 256, 256>>>(Wout, woh, wol,
                                                     DM_ * DM_ / 4);

    // 1) QKV projection (HMMA)
    dim3 g1(3 * DM_ / 128, M_ / 128);
    gemm_mma_bf16x3<<<g1, 256>>>(xh, xl, wqh, wql, bqkv, qkv, M_, 3 * DM_, DM_);

    // 2) RoPE + split whole qkv to bf16 hi/lo
    rope_split<<<(M_ * (ROWSTRIDE / 2)) / 256, 256>>>(qkv, qkvh, qkvl);

    // 3) Flash attention (HMMA 3-pass)
    dim3 g3(S_ / 128, B_ * H_);
    flash_mma<<<g3, 256, FLASH_SMEM_BYTES>>>(qkvh, qkvl, attn);

    // 4) split attention output, then out projection (HMMA)
    split_bf16<<<(M_ * DM_ / 4 + 255) / 256, 256>>>(attn, ah, al, M_ * DM_ / 4);
    dim3 g4(DM_ / 128, M_ / 128);
    gemm_mma_bf16x3<<<g4, 256>>>(ah, al, woh, wol, bout, out, M_, DM_, DM_);
}

// round 5
// speedup vs baseline: 1.5419x; 1.0270x over previous
#include <cuda_runtime.h>
#include <cuda_bf16.h>
#include <math.h>
#include <stdint.h>

// Problem constants
#define B_   2
#define S_   2048
#define DM_  1024
#define H_   16
#define DH_  64
#define M_   (B_ * S_)          // 4096 rows
#define ROWSTRIDE 3072          // qkv row stride (3*DM_)

// Scratch (allocation-free rule: __device__ globals)
__device__ float g_qkv[(size_t)M_ * 3 * DM_];
__device__ float g_attn[(size_t)M_ * DM_];
__device__ __nv_bfloat16 g_qkvh[(size_t)M_ * 3 * DM_];
__device__ __nv_bfloat16 g_qkvl[(size_t)M_ * 3 * DM_];
__device__ __nv_bfloat16 g_xh[(size_t)M_ * DM_];
__device__ __nv_bfloat16 g_xl[(size_t)M_ * DM_];
__device__ __nv_bfloat16 g_wqh[(size_t)3 * DM_ * DM_];
__device__ __nv_bfloat16 g_wql[(size_t)3 * DM_ * DM_];
__device__ __nv_bfloat16 g_woh[(size_t)DM_ * DM_];
__device__ __nv_bfloat16 g_wol[(size_t)DM_ * DM_];
__device__ __nv_bfloat16 g_ah[(size_t)M_ * DM_];
__device__ __nv_bfloat16 g_al[(size_t)M_ * DM_];

// ---------------------------------------------------------------------------
// PTX helpers
// ---------------------------------------------------------------------------
__device__ __forceinline__ uint32_t smem_u32(const void* p) {
    uint32_t a;
    asm("{ .reg .u64 t; cvta.to.shared.u64 t, %1; cvt.u32.u64 %0, t; }"
        : "=r"(a) : "l"(p));
    return a;
}

#define LDSM_X4(r0, r1, r2, r3, addr) \
    asm volatile("ldmatrix.sync.aligned.m8n8.x4.shared.b16 {%0,%1,%2,%3}, [%4];" \
                 : "=r"(r0), "=r"(r1), "=r"(r2), "=r"(r3) : "r"(addr))
#define LDSM_X4T(r0, r1, r2, r3, addr) \
    asm volatile("ldmatrix.sync.aligned.m8n8.x4.trans.shared.b16 {%0,%1,%2,%3}, [%4];" \
                 : "=r"(r0), "=r"(r1), "=r"(r2), "=r"(r3) : "r"(addr))
#define LDSM_X2(r0, r1, addr) \
    asm volatile("ldmatrix.sync.aligned.m8n8.x2.shared.b16 {%0,%1}, [%2];" \
                 : "=r"(r0), "=r"(r1) : "r"(addr))

#define CP_ASYNC16(dst, src) \
    asm volatile("cp.async.cg.shared.global [%0], [%1], 16;" \
                 :: "r"(dst), "l"(src))
#define CP_COMMIT() asm volatile("cp.async.commit_group;" ::: "memory")
#define CP_WAIT(n)  asm volatile("cp.async.wait_group %0;" :: "n"(n) : "memory")

__device__ __forceinline__ void mma16816(float* c, const uint32_t* a,
                                         const uint32_t* b) {
    asm volatile(
        "mma.sync.aligned.m16n8k16.row.col.f32.bf16.bf16.f32 "
        "{%0,%1,%2,%3}, {%4,%5,%6,%7}, {%8,%9}, {%0,%1,%2,%3};"
        : "+f"(c[0]), "+f"(c[1]), "+f"(c[2]), "+f"(c[3])
        : "r"(a[0]), "r"(a[1]), "r"(a[2]), "r"(a[3]), "r"(b[0]), "r"(b[1]));
}

__device__ __forceinline__ uint32_t packbf(float a, float b) {
    __nv_bfloat162 t = __float22bfloat162_rn(make_float2(a, b));
    return *(uint32_t*)&t;
}

// ---------------------------------------------------------------------------
// split: fp32 -> bf16 hi + bf16 lo
// ---------------------------------------------------------------------------
__global__ __launch_bounds__(256) void split_bf16(
    const float* __restrict__ src, __nv_bfloat16* __restrict__ hi,
    __nv_bfloat16* __restrict__ lo, int n4)
{
    int i = blockIdx.x * blockDim.x + threadIdx.x;
    if (i >= n4) return;
    float4 v = ((const float4*)src)[i];
    __nv_bfloat162 h0 = __float22bfloat162_rn(make_float2(v.x, v.y));
    __nv_bfloat162 h1 = __float22bfloat162_rn(make_float2(v.z, v.w));
    float2 b0 = __bfloat1622float2(h0);
    float2 b1 = __bfloat1622float2(h1);
    __nv_bfloat162 l0 = __float22bfloat162_rn(make_float2(v.x - b0.x, v.y - b0.y));
    __nv_bfloat162 l1 = __float22bfloat162_rn(make_float2(v.z - b1.x, v.w - b1.y));
    uint2 hp, lp;
    hp.x = *(uint32_t*)&h0; hp.y = *(uint32_t*)&h1;
    lp.x = *(uint32_t*)&l0; lp.y = *(uint32_t*)&l1;
    ((uint2*)hi)[i] = hp;
    ((uint2*)lo)[i] = lp;
}

// ---------------------------------------------------------------------------
// HMMA GEMM, split-bf16 3-pass, cp.async double-buffered.
// 128x128 CTA tile, BK=32, 8 warps (2M x 4N), warp tile 64x32.
// ---------------------------------------------------------------------------
#define BK 32
#define ASTR 40
#define STG_H (128 * ASTR)                    // halfs per tile buffer
#define GEMM_SMEM_BYTES (2 * 4 * STG_H * 2)   // 81920

__global__ __launch_bounds__(256) void gemm_mma_bf16x3(
    const __nv_bfloat16* __restrict__ Ah, const __nv_bfloat16* __restrict__ Al,
    const __nv_bfloat16* __restrict__ Bh, const __nv_bfloat16* __restrict__ Bl,
    const float* __restrict__ bias, float* __restrict__ C,
    int M, int N, int K)
{
    extern __shared__ __nv_bfloat16 gsm[];
    const uint32_t uG = smem_u32(gsm);

    const int tid = threadIdx.x;
    const int wid = tid >> 5;
    const int lane = tid & 31;
    const int warp_m = wid & 1;
    const int warp_n = wid >> 1;
    const int bm = blockIdx.y * 128;
    const int bn = blockIdx.x * 128;

    const __nv_bfloat16* src[4];
    src[0] = Ah + (size_t)bm * K;
    src[1] = Al + (size_t)bm * K;
    src[2] = Bh + (size_t)bn * K;
    src[3] = Bl + (size_t)bn * K;

    float acc[4][4][4];
#pragma unroll
    for (int i = 0; i < 4; i++)
#pragma unroll
        for (int j = 0; j < 4; j++)
#pragma unroll
            for (int e = 0; e < 4; e++) acc[i][j][e] = 0.f;

    const int row = tid >> 2;            // 0..63? no: tid/4 -> 0..63. Need 0..127
    // per prefetch iter: L = i*256+tid; row = L>>2 (0..127), c8 = (L&3)*8
    const int niter = K / BK;

    // prefetch stage 0
    {
#pragma unroll
        for (int i = 0; i < 2; i++) {
            int L = i * 256 + tid;
            int r = L >> 2, c8 = (L & 3) * 8;
            size_t g = (size_t)r * K + c8;
#pragma unroll
            for (int t4 = 0; t4 < 4; t4++) {
                uint32_t d = uG + (uint32_t)(t4 * STG_H + r * ASTR + c8) * 2;
                CP_ASYNC16(d, src[t4] + g);
            }
        }
        CP_COMMIT();
    }

    for (int it = 0; it < niter; it++) {
        const int stage = it & 1;
        if (it + 1 < niter) {
            const int k0 = (it + 1) * BK;
            const uint32_t sbase = (uint32_t)((stage ^ 1) * 4 * STG_H) * 2;
#pragma unroll
            for (int i = 0; i < 2; i++) {
                int L = i * 256 + tid;
                int r = L >> 2, c8 = (L & 3) * 8;
                size_t g = (size_t)r * K + k0 + c8;
#pragma unroll
                for (int t4 = 0; t4 < 4; t4++) {
                    uint32_t d = uG + sbase + (uint32_t)(t4 * STG_H + r * ASTR + c8) * 2;
                    CP_ASYNC16(d, src[t4] + g);
                }
            }
            CP_COMMIT();
            CP_WAIT(1);
        } else {
            CP_WAIT(0);
        }
        __syncthreads();

        const uint32_t uAh = uG + (uint32_t)(stage * 4 * STG_H) * 2;
        const uint32_t uAl = uAh + STG_H * 2;
        const uint32_t uBh = uAl + STG_H * 2;
        const uint32_t uBl = uBh + STG_H * 2;

#pragma unroll
        for (int ks = 0; ks < 2; ks++) {
            uint32_t ah[4][4], al[4][4], bh[4][2], bl[4][2];
            const int kof = ks * 16 + (lane >> 4) * 8;
            const int kofb = ks * 16 + ((lane >> 3) & 1) * 8;
#pragma unroll
            for (int mi = 0; mi < 4; mi++) {
                uint32_t r = (uint32_t)((warp_m * 64 + mi * 16 + (lane & 15)) * ASTR + kof) * 2;
                LDSM_X4(ah[mi][0], ah[mi][1], ah[mi][2], ah[mi][3], uAh + r);
                LDSM_X4(al[mi][0], al[mi][1], al[mi][2], al[mi][3], uAl + r);
            }
#pragma unroll
            for (int ni = 0; ni < 4; ni++) {
                uint32_t r = (uint32_t)((warp_n * 32 + ni * 8 + (lane & 7)) * ASTR + kofb) * 2;
                LDSM_X2(bh[ni][0], bh[ni][1], uBh + r);
                LDSM_X2(bl[ni][0], bl[ni][1], uBl + r);
            }
#pragma unroll
            for (int mi = 0; mi < 4; mi++)
#pragma unroll
                for (int ni = 0; ni < 4; ni++) {
                    mma16816(acc[mi][ni], ah[mi], bh[ni]);
                    mma16816(acc[mi][ni], ah[mi], bl[ni]);
                    mma16816(acc[mi][ni], al[mi], bh[ni]);
                }
        }
        __syncthreads();
    }

    const int m0 = bm + warp_m * 64;
    const int n0 = bn + warp_n * 32;
#pragma unroll
    for (int mi = 0; mi < 4; mi++) {
#pragma unroll
        for (int ni = 0; ni < 4; ni++) {
            int col = n0 + ni * 8 + (lane & 3) * 2;
            float2 bv = *(const float2*)(bias + col);
            int r0 = m0 + mi * 16 + (lane >> 2);
            float2 o0, o1;
            o0.x = acc[mi][ni][0] + bv.x;
            o0.y = acc[mi][ni][1] + bv.y;
            o1.x = acc[mi][ni][2] + bv.x;
            o1.y = acc[mi][ni][3] + bv.y;
            *(float2*)(C + (size_t)r0 * N + col) = o0;
            *(float2*)(C + (size_t)(r0 + 8) * N + col) = o1;
        }
    }
}

// ---------------------------------------------------------------------------
// RoPE + hi/lo split of the whole qkv tensor
// ---------------------------------------------------------------------------
__global__ __launch_bounds__(256) void rope_split(
    const float* __restrict__ qkv, __nv_bfloat16* __restrict__ oh,
    __nv_bfloat16* __restrict__ ol)
{
    int idx = blockIdx.x * blockDim.x + threadIdx.x;
    if (idx >= M_ * (ROWSTRIDE / 2)) return;
    int row = idx / (ROWSTRIDE / 2);
    int col = (idx % (ROWSTRIDE / 2)) * 2;
    float2 v = *(const float2*)(qkv + (size_t)row * ROWSTRIDE + col);
    int sec = col >> 10;
    int p = (col & 63) >> 1;
    if (sec < 2 && p < 16) {
        int s = row & (S_ - 1);
        float inv_freq = (float)pow(10000.0, -(double)p / 16.0);
        float sn, cs;
        sincosf((float)s * inv_freq, &sn, &cs);
        float x1 = v.x, x2 = v.y;
        v.x = x1 * cs - x2 * sn;
        v.y = x2 * cs + x1 * sn;
    }
    __nv_bfloat162 hh = __float22bfloat162_rn(v);
    float2 back = __bfloat1622float2(hh);
    __nv_bfloat162 ll = __float22bfloat162_rn(make_float2(v.x - back.x, v.y - back.y));
    *(__nv_bfloat162*)(oh + (size_t)row * ROWSTRIDE + col) = hh;
    *(__nv_bfloat162*)(ol + (size_t)row * ROWSTRIDE + col) = ll;
}

// ---------------------------------------------------------------------------
// Flash attention via HMMA, 3-pass split-bf16; Q fragments register-resident;
// 64-key smem tiles processed in 32-key halves; X4 ldmatrix for K and V.
// ---------------------------------------------------------------------------
#define FST 72
#define FLASH_SMEM_BYTES (4 * 64 * FST * 2)   // 36864 (also Q staging: 2*128*FST*2)

__global__ __launch_bounds__(256, 2) void flash_mma(
    const __nv_bfloat16* __restrict__ qkvh,
    const __nv_bfloat16* __restrict__ qkvl,
    float* __restrict__ outp)
{
    extern __shared__ __nv_bfloat16 fsm[];
    const uint32_t uF = smem_u32(fsm);
    const uint32_t uKh = uF;
    const uint32_t uKl = uF + 64 * FST * 2;
    const uint32_t uVh = uF + 128 * FST * 2;
    const uint32_t uVl = uF + 192 * FST * 2;

    const int tid = threadIdx.x;
    const int wid = tid >> 5, lane = tid & 31;
    const int bhid = blockIdx.y;
    const int bb = bhid >> 4, h = bhid & 15;
    const int q0 = blockIdx.x * 128;

    const size_t rowbase = (size_t)bb * S_ * ROWSTRIDE;
    const __nv_bfloat16* qbh = qkvh + rowbase + h * DH_;
    const __nv_bfloat16* qbl = qkvl + rowbase + h * DH_;

    // --- Stage Q (128 x 64, hi & lo) into smem, lift fragments to registers
#pragma unroll
    for (int it = 0; it < 4; it++) {
        int L = it * 256 + tid;
        int r = L >> 3, c8 = (L & 7) * 8;
        size_t g = (size_t)(q0 + r) * ROWSTRIDE + c8;
        *(uint4*)(fsm + r * FST + c8) = *(const uint4*)(qbh + g);
        *(uint4*)(fsm + 128 * FST + r * FST + c8) = *(const uint4*)(qbl + g);
    }
    __syncthreads();

    uint32_t qh[4][4], ql[4][4];
#pragma unroll
    for (int kc = 0; kc < 4; kc++) {
        uint32_t qa = (uint32_t)((wid * 16 + (lane & 15)) * FST + kc * 16
                                 + 8 * (lane >> 4)) * 2;
        LDSM_X4(qh[kc][0], qh[kc][1], qh[kc][2], qh[kc][3], uF + qa);
        LDSM_X4(ql[kc][0], ql[kc][1], ql[kc][2], ql[kc][3],
                uF + 128 * FST * 2 + qa);
    }
    __syncthreads();

    float o[8][4];
#pragma unroll
    for (int ni = 0; ni < 8; ni++)
#pragma unroll
        for (int e = 0; e < 4; e++) o[ni][e] = 0.f;
    float m0 = -INFINITY, m1 = -INFINITY, l0 = 0.f, l1 = 0.f;

    const float scale = 0.125f;
    const int q8 = lane >> 3;            // quad-pair id for X4 addressing
    const int l7 = lane & 7;

    for (int t = 0; t < S_ / 64; t++) {
        // Load K/V tiles (hi & lo), 64 x 64 each
#pragma unroll
        for (int it = 0; it < 8; it++) {
            int L = it * 256 + tid;
            int tsel = L >> 9;
            int r = (L >> 3) & 63, c8 = (L & 7) * 8;
            size_t g = (size_t)(t * 64 + r) * ROWSTRIDE + c8;
            const __nv_bfloat16* srcp =
                (tsel == 0) ? qbh + DM_ : (tsel == 1) ? qbl + DM_ :
                (tsel == 2) ? qbh + 2 * DM_ : qbl + 2 * DM_;
            __nv_bfloat16* dst = fsm + tsel * 64 * FST;
            *(uint4*)(dst + r * FST + c8) = *(const uint4*)(srcp + g);
        }
        __syncthreads();

#pragma unroll
        for (int half = 0; half < 2; half++) {
            // ---- S = Q @ K^T over 32 keys
            float s[4][4];
#pragma unroll
            for (int ni = 0; ni < 4; ni++)
#pragma unroll
                for (int e = 0; e < 4; e++) s[ni][e] = 0.f;

#pragma unroll
            for (int kc = 0; kc < 4; kc++) {
#pragma unroll
                for (int ni2 = 0; ni2 < 2; ni2++) {
                    uint32_t ka = (uint32_t)(
                        (half * 32 + ni2 * 16 + (q8 >> 1) * 8 + l7) * FST
                        + kc * 16 + (q8 & 1) * 8) * 2;
                    uint32_t kh4[4], kl4[4];
                    LDSM_X4(kh4[0], kh4[1], kh4[2], kh4[3], uKh + ka);
                    LDSM_X4(kl4[0], kl4[1], kl4[2], kl4[3], uKl + ka);
                    mma16816(s[ni2 * 2], qh[kc], kh4);
                    mma16816(s[ni2 * 2], qh[kc], kl4);
                    mma16816(s[ni2 * 2], ql[kc], kh4);
                    mma16816(s[ni2 * 2 + 1], qh[kc], kh4 + 2);
                    mma16816(s[ni2 * 2 + 1], qh[kc], kl4 + 2);
                    mma16816(s[ni2 * 2 + 1], ql[kc], kh4 + 2);
                }
            }

            // ---- online softmax (32 keys), warp-local
#pragma unroll
            for (int ni = 0; ni < 4; ni++)
#pragma unroll
                for (int e = 0; e < 4; e++) s[ni][e] *= scale;

            float rm0 = -INFINITY, rm1 = -INFINITY;
#pragma unroll
            for (int ni = 0; ni < 4; ni++) {
                rm0 = fmaxf(rm0, fmaxf(s[ni][0], s[ni][1]));
                rm1 = fmaxf(rm1, fmaxf(s[ni][2], s[ni][3]));
            }
            rm0 = fmaxf(rm0, __shfl_xor_sync(0xffffffffu, rm0, 1));
            rm0 = fmaxf(rm0, __shfl_xor_sync(0xffffffffu, rm0, 2));
            rm1 = fmaxf(rm1, __shfl_xor_sync(0xffffffffu, rm1, 1));
            rm1 = fmaxf(rm1, __shfl_xor_sync(0xffffffffu, rm1, 2));

            float mn0 = fmaxf(m0, rm0), mn1 = fmaxf(m1, rm1);
            float c0 = __expf(m0 - mn0), c1 = __expf(m1 - mn1);
            m0 = mn0; m1 = mn1;

            float rs0 = 0.f, rs1 = 0.f;
#pragma unroll
            for (int ni = 0; ni < 4; ni++) {
                s[ni][0] = __expf(s[ni][0] - mn0);
                s[ni][1] = __expf(s[ni][1] - mn0);
                s[ni][2] = __expf(s[ni][2] - mn1);
                s[ni][3] = __expf(s[ni][3] - mn1);
                rs0 += s[ni][0] + s[ni][1];
                rs1 += s[ni][2] + s[ni][3];
            }
            rs0 += __shfl_xor_sync(0xffffffffu, rs0, 1);
            rs0 += __shfl_xor_sync(0xffffffffu, rs0, 2);
            rs1 += __shfl_xor_sync(0xffffffffu, rs1, 1);
            rs1 += __shfl_xor_sync(0xffffffffu, rs1, 2);
            l0 = l0 * c0 + rs0;
            l1 = l1 * c1 + rs1;

#pragma unroll
            for (int ni = 0; ni < 8; ni++) {
                o[ni][0] *= c0; o[ni][1] *= c0;
                o[ni][2] *= c1; o[ni][3] *= c1;
            }

            // ---- pack P -> bf16 hi/lo A-fragments (registers only)
            uint32_t ph[4][2], pl[4][2];
#pragma unroll
            for (int ni = 0; ni < 4; ni++) {
                ph[ni][0] = packbf(s[ni][0], s[ni][1]);
                ph[ni][1] = packbf(s[ni][2], s[ni][3]);
                __nv_bfloat162 b0 = *(__nv_bfloat162*)&ph[ni][0];
                __nv_bfloat162 b1 = *(__nv_bfloat162*)&ph[ni][1];
                float2 f0 = __bfloat1622float2(b0);
                float2 f1 = __bfloat1622float2(b1);
                pl[ni][0] = packbf(s[ni][0] - f0.x, s[ni][1] - f0.y);
                pl[ni][1] = packbf(s[ni][2] - f1.x, s[ni][3] - f1.y);
            }

            // ---- O += P @ V over 32 keys
#pragma unroll
            for (int kc2 = 0; kc2 < 2; kc2++) {
                uint32_t af[4] = {ph[2 * kc2][0], ph[2 * kc2][1],
                                  ph[2 * kc2 + 1][0], ph[2 * kc2 + 1][1]};
                uint32_t alf[4] = {pl[2 * kc2][0], pl[2 * kc2][1],
                                   pl[2 * kc2 + 1][0], pl[2 * kc2 + 1][1]};
#pragma unroll
                for (int ni2 = 0; ni2 < 4; ni2++) {
                    uint32_t va = (uint32_t)(
                        (half * 32 + kc2 * 16 + (q8 & 1) * 8 + l7) * FST
                        + ni2 * 16 + (q8 >> 1) * 8) * 2;
                    uint32_t vh4[4], vl4[4];
                    LDSM_X4T(vh4[0], vh4[1], vh4[2], vh4[3], uVh + va);
                    LDSM_X4T(vl4[0], vl4[1], vl4[2], vl4[3], uVl + va);
                    mma16816(o[ni2 * 2], af, vh4);
                    mma16816(o[ni2 * 2], af, vl4);
                    mma16816(o[ni2 * 2], alf, vh4);
                    mma16816(o[ni2 * 2 + 1], af, vh4 + 2);
                    mma16816(o[ni2 * 2 + 1], af, vl4 + 2);
                    mma16816(o[ni2 * 2 + 1], alf, vh4 + 2);
                }
            }
        }
        __syncthreads();
    }

    // Epilogue
    float inv0 = 1.f / l0, inv1 = 1.f / l1;
    int r0 = q0 + wid * 16 + (lane >> 2);
    float* obase = outp + ((size_t)bb * S_ + r0) * DM_ + h * DH_;
#pragma unroll
    for (int ni = 0; ni < 8; ni++) {
        int col = ni * 8 + (lane & 3) * 2;
        float2 w0, w1;
        w0.x = o[ni][0] * inv0; w0.y = o[ni][1] * inv0;
        w1.x = o[ni][2] * inv1; w1.y = o[ni][3] * inv1;
        *(float2*)(obase + col) = w0;
        *(float2*)(obase + 8 * DM_ + col) = w1;
    }
}

// ---------------------------------------------------------------------------
extern "C" void kernel_launch(void* const* d_in, const int* in_sizes, int n_in,
                              void* d_out, int out_size)
{
    const float* x    = (const float*)d_in[0];
    const float* Wqkv = (const float*)d_in[1];
    const float* bqkv = (const float*)d_in[2];
    const float* Wout = (const float*)d_in[3];
    const float* bout = (const float*)d_in[4];
    float* out = (float*)d_out;

    float *qkv = nullptr, *attn = nullptr;
    __nv_bfloat16 *qkvh, *qkvl, *xh, *xl, *wqh, *wql, *woh, *wol, *ah, *al;
    cudaGetSymbolAddress((void**)&qkv, g_qkv);
    cudaGetSymbolAddress((void**)&attn, g_attn);
    cudaGetSymbolAddress((void**)&qkvh, g_qkvh);
    cudaGetSymbolAddress((void**)&qkvl, g_qkvl);
    cudaGetSymbolAddress((void**)&xh, g_xh);
    cudaGetSymbolAddress((void**)&xl, g_xl);
    cudaGetSymbolAddress((void**)&wqh, g_wqh);
    cudaGetSymbolAddress((void**)&wql, g_wql);
    cudaGetSymbolAddress((void**)&woh, g_woh);
    cudaGetSymbolAddress((void**)&wol, g_wol);
    cudaGetSymbolAddress((void**)&ah, g_ah);
    cudaGetSymbolAddress((void**)&al, g_al);

    cudaFuncSetAttribute(gemm_mma_bf16x3,
                         cudaFuncAttributeMaxDynamicSharedMemorySize,
                         GEMM_SMEM_BYTES);
    cudaFuncSetAttribute(flash_mma, cudaFuncAttributeMaxDynamicSharedMemorySize,
                         FLASH_SMEM_BYTES);

    // 0) split inputs to bf16 hi/lo
    split_bf16<<<(M_ * DM_ / 4 + 255) / 256, 256>>>(x, xh, xl, M_ * DM_ / 4);
    split_bf16<<<(3 * DM_ * DM_ / 4 + 255) / 256, 256>>>(Wqkv, wqh, wql,
                                                         3 * DM_ * DM_ / 4);
    split_bf16<<<(DM_ * DM_ / 4 + 255) / 256, 256>>>(Wout, woh, wol,
                                                     DM_ * DM_ / 4);

    // 1) QKV projection (HMMA, double-buffered)
    dim3 g1(3 * DM_ / 128, M_ / 128);
    gemm_mma_bf16x3<<<g1, 256, GEMM_SMEM_BYTES>>>(xh, xl, wqh, wql, bqkv, qkv,
                                                  M_, 3 * DM_, DM_);

    // 2) RoPE + split whole qkv to bf16 hi/lo
    rope_split<<<(M_ * (ROWSTRIDE / 2)) / 256, 256>>>(qkv, qkvh, qkvl);

    // 3) Flash attention (HMMA 3-pass, register-resident Q)
    dim3 g3(S_ / 128, B_ * H_);
    flash_mma<<<g3, 256, FLASH_SMEM_BYTES>>>(qkvh, qkvl, attn);

    // 4) split attention output, then out projection (HMMA)
    split_bf16<<<(M_ * DM_ / 4 + 255) / 256, 256>>>(attn, ah, al, M_ * DM_ / 4);
    dim3 g4(DM_ / 128, M_ / 128);
    gemm_mma_bf16x3<<<g4, 256, GEMM_SMEM_BYTES>>>(ah, al, woh, wol, bout, out,
                                                  M_, DM_, DM_);
}

// round 6
// speedup vs baseline: 1.8009x; 1.1680x over previous
#include <cuda_runtime.h>
#include <cuda_bf16.h>
#include <cuda_fp16.h>
#include <math.h>
#include <stdint.h>

// Problem constants
#define B_   2
#define S_   2048
#define DM_  1024
#define H_   16
#define DH_  64
#define M_   (B_ * S_)          // 4096 rows
#define ROWSTRIDE 3072          // qkv row stride (3*DM_)

// Scratch (allocation-free rule: __device__ globals)
__device__ float g_qkv[(size_t)M_ * 3 * DM_];
__device__ float g_attn[(size_t)M_ * DM_];
__device__ __half g_qkv16[(size_t)M_ * 3 * DM_];
__device__ __nv_bfloat16 g_xh[(size_t)M_ * DM_];
__device__ __nv_bfloat16 g_xl[(size_t)M_ * DM_];
__device__ __nv_bfloat16 g_wqh[(size_t)3 * DM_ * DM_];
__device__ __nv_bfloat16 g_wql[(size_t)3 * DM_ * DM_];
__device__ __nv_bfloat16 g_woh[(size_t)DM_ * DM_];
__device__ __nv_bfloat16 g_wol[(size_t)DM_ * DM_];
__device__ __nv_bfloat16 g_ah[(size_t)M_ * DM_];
__device__ __nv_bfloat16 g_al[(size_t)M_ * DM_];

// ---------------------------------------------------------------------------
// PTX helpers
// ---------------------------------------------------------------------------
__device__ __forceinline__ uint32_t smem_u32(const void* p) {
    uint32_t a;
    asm("{ .reg .u64 t; cvta.to.shared.u64 t, %1; cvt.u32.u64 %0, t; }"
        : "=r"(a) : "l"(p));
    return a;
}

#define LDSM_X4(r0, r1, r2, r3, addr) \
    asm volatile("ldmatrix.sync.aligned.m8n8.x4.shared.b16 {%0,%1,%2,%3}, [%4];" \
                 : "=r"(r0), "=r"(r1), "=r"(r2), "=r"(r3) : "r"(addr))
#define LDSM_X4T(r0, r1, r2, r3, addr) \
    asm volatile("ldmatrix.sync.aligned.m8n8.x4.trans.shared.b16 {%0,%1,%2,%3}, [%4];" \
                 : "=r"(r0), "=r"(r1), "=r"(r2), "=r"(r3) : "r"(addr))
#define LDSM_X2(r0, r1, addr) \
    asm volatile("ldmatrix.sync.aligned.m8n8.x2.shared.b16 {%0,%1}, [%2];" \
                 : "=r"(r0), "=r"(r1) : "r"(addr))

#define CP_ASYNC16(dst, src) \
    asm volatile("cp.async.cg.shared.global [%0], [%1], 16;" \
                 :: "r"(dst), "l"(src))
#define CP_COMMIT() asm volatile("cp.async.commit_group;" ::: "memory")
#define CP_WAIT(n)  asm volatile("cp.async.wait_group %0;" :: "n"(n) : "memory")

// bf16 mma (projections)
__device__ __forceinline__ void mma16816(float* c, const uint32_t* a,
                                         const uint32_t* b) {
    asm volatile(
        "mma.sync.aligned.m16n8k16.row.col.f32.bf16.bf16.f32 "
        "{%0,%1,%2,%3}, {%4,%5,%6,%7}, {%8,%9}, {%0,%1,%2,%3};"
        : "+f"(c[0]), "+f"(c[1]), "+f"(c[2]), "+f"(c[3])
        : "r"(a[0]), "r"(a[1]), "r"(a[2]), "r"(a[3]), "r"(b[0]), "r"(b[1]));
}
// fp16 mma (attention)
__device__ __forceinline__ void mma16816h(float* c, const uint32_t* a,
                                          const uint32_t* b) {
    asm volatile(
        "mma.sync.aligned.m16n8k16.row.col.f32.f16.f16.f32 "
        "{%0,%1,%2,%3}, {%4,%5,%6,%7}, {%8,%9}, {%0,%1,%2,%3};"
        : "+f"(c[0]), "+f"(c[1]), "+f"(c[2]), "+f"(c[3])
        : "r"(a[0]), "r"(a[1]), "r"(a[2]), "r"(a[3]), "r"(b[0]), "r"(b[1]));
}

__device__ __forceinline__ uint32_t packh(float a, float b) {
    __half2 t = __float22half2_rn(make_float2(a, b));
    return *(uint32_t*)&t;
}

// ---------------------------------------------------------------------------
// split: fp32 -> bf16 hi + bf16 lo
// ---------------------------------------------------------------------------
__global__ __launch_bounds__(256) void split_bf16(
    const float* __restrict__ src, __nv_bfloat16* __restrict__ hi,
    __nv_bfloat16* __restrict__ lo, int n4)
{
    int i = blockIdx.x * blockDim.x + threadIdx.x;
    if (i >= n4) return;
    float4 v = ((const float4*)src)[i];
    __nv_bfloat162 h0 = __float22bfloat162_rn(make_float2(v.x, v.y));
    __nv_bfloat162 h1 = __float22bfloat162_rn(make_float2(v.z, v.w));
    float2 b0 = __bfloat1622float2(h0);
    float2 b1 = __bfloat1622float2(h1);
    __nv_bfloat162 l0 = __float22bfloat162_rn(make_float2(v.x - b0.x, v.y - b0.y));
    __nv_bfloat162 l1 = __float22bfloat162_rn(make_float2(v.z - b1.x, v.w - b1.y));
    uint2 hp, lp;
    hp.x = *(uint32_t*)&h0; hp.y = *(uint32_t*)&h1;
    lp.x = *(uint32_t*)&l0; lp.y = *(uint32_t*)&l1;
    ((uint2*)hi)[i] = hp;
    ((uint2*)lo)[i] = lp;
}

// ---------------------------------------------------------------------------
// HMMA GEMM, split-bf16 3-pass, cp.async double-buffered. (round 5, unchanged)
// ---------------------------------------------------------------------------
#define BK 32
#define ASTR 40
#define STG_H (128 * ASTR)
#define GEMM_SMEM_BYTES (2 * 4 * STG_H * 2)

__global__ __launch_bounds__(256) void gemm_mma_bf16x3(
    const __nv_bfloat16* __restrict__ Ah, const __nv_bfloat16* __restrict__ Al,
    const __nv_bfloat16* __restrict__ Bh, const __nv_bfloat16* __restrict__ Bl,
    const float* __restrict__ bias, float* __restrict__ C,
    int M, int N, int K)
{
    extern __shared__ __nv_bfloat16 gsm[];
    const uint32_t uG = smem_u32(gsm);

    const int tid = threadIdx.x;
    const int wid = tid >> 5;
    const int lane = tid & 31;
    const int warp_m = wid & 1;
    const int warp_n = wid >> 1;
    const int bm = blockIdx.y * 128;
    const int bn = blockIdx.x * 128;

    const __nv_bfloat16* src[4];
    src[0] = Ah + (size_t)bm * K;
    src[1] = Al + (size_t)bm * K;
    src[2] = Bh + (size_t)bn * K;
    src[3] = Bl + (size_t)bn * K;

    float acc[4][4][4];
#pragma unroll
    for (int i = 0; i < 4; i++)
#pragma unroll
        for (int j = 0; j < 4; j++)
#pragma unroll
            for (int e = 0; e < 4; e++) acc[i][j][e] = 0.f;

    const int niter = K / BK;
    {
#pragma unroll
        for (int i = 0; i < 2; i++) {
            int L = i * 256 + tid;
            int r = L >> 2, c8 = (L & 3) * 8;
            size_t g = (size_t)r * K + c8;
#pragma unroll
            for (int t4 = 0; t4 < 4; t4++) {
                uint32_t d = uG + (uint32_t)(t4 * STG_H + r * ASTR + c8) * 2;
                CP_ASYNC16(d, src[t4] + g);
            }
        }
        CP_COMMIT();
    }

    for (int it = 0; it < niter; it++) {
        const int stage = it & 1;
        if (it + 1 < niter) {
            const int k0 = (it + 1) * BK;
            const uint32_t sbase = (uint32_t)((stage ^ 1) * 4 * STG_H) * 2;
#pragma unroll
            for (int i = 0; i < 2; i++) {
                int L = i * 256 + tid;
                int r = L >> 2, c8 = (L & 3) * 8;
                size_t g = (size_t)r * K + k0 + c8;
#pragma unroll
                for (int t4 = 0; t4 < 4; t4++) {
                    uint32_t d = uG + sbase + (uint32_t)(t4 * STG_H + r * ASTR + c8) * 2;
                    CP_ASYNC16(d, src[t4] + g);
                }
            }
            CP_COMMIT();
            CP_WAIT(1);
        } else {
            CP_WAIT(0);
        }
        __syncthreads();

        const uint32_t uAh = uG + (uint32_t)(stage * 4 * STG_H) * 2;
        const uint32_t uAl = uAh + STG_H * 2;
        const uint32_t uBh = uAl + STG_H * 2;
        const uint32_t uBl = uBh + STG_H * 2;

#pragma unroll
        for (int ks = 0; ks < 2; ks++) {
            uint32_t ah[4][4], al[4][4], bh[4][2], bl[4][2];
            const int kof = ks * 16 + (lane >> 4) * 8;
            const int kofb = ks * 16 + ((lane >> 3) & 1) * 8;
#pragma unroll
            for (int mi = 0; mi < 4; mi++) {
                uint32_t r = (uint32_t)((warp_m * 64 + mi * 16 + (lane & 15)) * ASTR + kof) * 2;
                LDSM_X4(ah[mi][0], ah[mi][1], ah[mi][2], ah[mi][3], uAh + r);
                LDSM_X4(al[mi][0], al[mi][1], al[mi][2], al[mi][3], uAl + r);
            }
#pragma unroll
            for (int ni = 0; ni < 4; ni++) {
                uint32_t r = (uint32_t)((warp_n * 32 + ni * 8 + (lane & 7)) * ASTR + kofb) * 2;
                LDSM_X2(bh[ni][0], bh[ni][1], uBh + r);
                LDSM_X2(bl[ni][0], bl[ni][1], uBl + r);
            }
#pragma unroll
            for (int mi = 0; mi < 4; mi++)
#pragma unroll
                for (int ni = 0; ni < 4; ni++) {
                    mma16816(acc[mi][ni], ah[mi], bh[ni]);
                    mma16816(acc[mi][ni], ah[mi], bl[ni]);
                    mma16816(acc[mi][ni], al[mi], bh[ni]);
                }
        }
        __syncthreads();
    }

    const int m0 = bm + warp_m * 64;
    const int n0 = bn + warp_n * 32;
#pragma unroll
    for (int mi = 0; mi < 4; mi++) {
#pragma unroll
        for (int ni = 0; ni < 4; ni++) {
            int col = n0 + ni * 8 + (lane & 3) * 2;
            float2 bv = *(const float2*)(bias + col);
            int r0 = m0 + mi * 16 + (lane >> 2);
            float2 o0, o1;
            o0.x = acc[mi][ni][0] + bv.x;
            o0.y = acc[mi][ni][1] + bv.y;
            o1.x = acc[mi][ni][2] + bv.x;
            o1.y = acc[mi][ni][3] + bv.y;
            *(float2*)(C + (size_t)r0 * N + col) = o0;
            *(float2*)(C + (size_t)(r0 + 8) * N + col) = o1;
        }
    }
}

// ---------------------------------------------------------------------------
// RoPE + fp16 convert of the whole qkv tensor; q is pre-scaled by 1/sqrt(Dh).
// ---------------------------------------------------------------------------
__global__ __launch_bounds__(256) void rope_h16(
    const float* __restrict__ qkv, __half* __restrict__ o16)
{
    int idx = blockIdx.x * blockDim.x + threadIdx.x;
    if (idx >= M_ * (ROWSTRIDE / 2)) return;
    int row = idx / (ROWSTRIDE / 2);
    int col = (idx % (ROWSTRIDE / 2)) * 2;
    float2 v = *(const float2*)(qkv + (size_t)row * ROWSTRIDE + col);
    int sec = col >> 10;                 // 0=q 1=k 2=v
    int p = (col & 63) >> 1;
    if (sec < 2 && p < 16) {
        int s = row & (S_ - 1);
        float inv_freq = (float)pow(10000.0, -(double)p / 16.0);
        float sn, cs;
        sincosf((float)s * inv_freq, &sn, &cs);
        float x1 = v.x, x2 = v.y;
        v.x = x1 * cs - x2 * sn;
        v.y = x2 * cs + x1 * sn;
    }
    if (sec == 0) { v.x *= 0.125f; v.y *= 0.125f; }
    *(__half2*)(o16 + (size_t)row * ROWSTRIDE + col) =
        __float22half2_rn(v);
}

// ---------------------------------------------------------------------------
// Flash attention, single-pass fp16 HMMA. Q fragments register-resident;
// K/V double-buffered via cp.async. 8 warps x 16 query rows, 64-key tiles.
// ---------------------------------------------------------------------------
#define FST 72
#define KVT (64 * FST)                       // halfs per K or V tile
#define FLASH_SMEM_BYTES (2 * 2 * KVT * 2)   // 36864 (Q staging fits inside)

__global__ __launch_bounds__(256, 2) void flash_h16(
    const __half* __restrict__ qkv16, float* __restrict__ outp)
{
    extern __shared__ __half hsm[];
    const uint32_t uF = smem_u32(hsm);

    const int tid = threadIdx.x;
    const int wid = tid >> 5, lane = tid & 31;
    const int bhid = blockIdx.y;
    const int bb = bhid >> 4, h = bhid & 15;
    const int q0 = blockIdx.x * 128;

    const size_t rowbase = (size_t)bb * S_ * ROWSTRIDE;
    const __half* qb = qkv16 + rowbase + h * DH_;
    const __half* kb = qb + DM_;
    const __half* vb = qb + 2 * DM_;

    // --- Stage Q (128 x 64 halfs) into smem, lift fragments to registers
#pragma unroll
    for (int it = 0; it < 4; it++) {
        int L = it * 256 + tid;
        int r = L >> 3, c8 = (L & 7) * 8;
        size_t g = (size_t)(q0 + r) * ROWSTRIDE + c8;
        *(uint4*)(hsm + r * FST + c8) = *(const uint4*)(qb + g);
    }
    __syncthreads();

    uint32_t qf[4][4];
#pragma unroll
    for (int kc = 0; kc < 4; kc++) {
        uint32_t qa = (uint32_t)((wid * 16 + (lane & 15)) * FST + kc * 16
                                 + 8 * (lane >> 4)) * 2;
        LDSM_X4(qf[kc][0], qf[kc][1], qf[kc][2], qf[kc][3], uF + qa);
    }
    __syncthreads();

    float o[8][4];
#pragma unroll
    for (int ni = 0; ni < 8; ni++)
#pragma unroll
        for (int e = 0; e < 4; e++) o[ni][e] = 0.f;
    float m0 = -INFINITY, m1 = -INFINITY, l0 = 0.f, l1 = 0.f;

    const int q8 = lane >> 3;
    const int l7 = lane & 7;

    // prefetch tile 0
    {
#pragma unroll
        for (int it = 0; it < 4; it++) {
            int L = it * 256 + tid;
            int tsel = L >> 9;
            int r = (L >> 3) & 63, c8 = (L & 7) * 8;
            const __half* srcp = (tsel == 0 ? kb : vb)
                                 + (size_t)r * ROWSTRIDE + c8;
            uint32_t d = uF + (uint32_t)(tsel * KVT + r * FST + c8) * 2;
            CP_ASYNC16(d, srcp);
        }
        CP_COMMIT();
    }

    for (int t = 0; t < S_ / 64; t++) {
        const int st = t & 1;
        if (t + 1 < S_ / 64) {
            const uint32_t sbase = (uint32_t)((st ^ 1) * 2 * KVT) * 2;
#pragma unroll
            for (int it = 0; it < 4; it++) {
                int L = it * 256 + tid;
                int tsel = L >> 9;
                int r = (L >> 3) & 63, c8 = (L & 7) * 8;
                const __half* srcp = (tsel == 0 ? kb : vb)
                                     + (size_t)((t + 1) * 64 + r) * ROWSTRIDE + c8;
                uint32_t d = uF + sbase + (uint32_t)(tsel * KVT + r * FST + c8) * 2;
                CP_ASYNC16(d, srcp);
            }
            CP_COMMIT();
            CP_WAIT(1);
        } else {
            CP_WAIT(0);
        }
        __syncthreads();

        const uint32_t uK = uF + (uint32_t)(st * 2 * KVT) * 2;
        const uint32_t uV = uK + (uint32_t)KVT * 2;

        // ---- S = Q @ K^T over 64 keys (single fp16 pass)
        float s[8][4];
#pragma unroll
        for (int ni = 0; ni < 8; ni++)
#pragma unroll
            for (int e = 0; e < 4; e++) s[ni][e] = 0.f;

#pragma unroll
        for (int kc = 0; kc < 4; kc++) {
#pragma unroll
            for (int ni2 = 0; ni2 < 4; ni2++) {
                uint32_t ka = (uint32_t)(
                    (ni2 * 16 + (q8 >> 1) * 8 + l7) * FST
                    + kc * 16 + (q8 & 1) * 8) * 2;
                uint32_t k4[4];
                LDSM_X4(k4[0], k4[1], k4[2], k4[3], uK + ka);
                mma16816h(s[ni2 * 2], qf[kc], k4);
                mma16816h(s[ni2 * 2 + 1], qf[kc], k4 + 2);
            }
        }

        // ---- online softmax (scale pre-applied to q)
        float rm0 = -INFINITY, rm1 = -INFINITY;
#pragma unroll
        for (int ni = 0; ni < 8; ni++) {
            rm0 = fmaxf(rm0, fmaxf(s[ni][0], s[ni][1]));
            rm1 = fmaxf(rm1, fmaxf(s[ni][2], s[ni][3]));
        }
        rm0 = fmaxf(rm0, __shfl_xor_sync(0xffffffffu, rm0, 1));
        rm0 = fmaxf(rm0, __shfl_xor_sync(0xffffffffu, rm0, 2));
        rm1 = fmaxf(rm1, __shfl_xor_sync(0xffffffffu, rm1, 1));
        rm1 = fmaxf(rm1, __shfl_xor_sync(0xffffffffu, rm1, 2));

        float mn0 = fmaxf(m0, rm0), mn1 = fmaxf(m1, rm1);
        float c0 = __expf(m0 - mn0), c1 = __expf(m1 - mn1);
        m0 = mn0; m1 = mn1;

        float rs0 = 0.f, rs1 = 0.f;
        uint32_t ph[8][2];
#pragma unroll
        for (int ni = 0; ni < 8; ni++) {
            s[ni][0] = __expf(s[ni][0] - mn0);
            s[ni][1] = __expf(s[ni][1] - mn0);
            s[ni][2] = __expf(s[ni][2] - mn1);
            s[ni][3] = __expf(s[ni][3] - mn1);
            rs0 += s[ni][0] + s[ni][1];
            rs1 += s[ni][2] + s[ni][3];
            ph[ni][0] = packh(s[ni][0], s[ni][1]);
            ph[ni][1] = packh(s[ni][2], s[ni][3]);
        }
        rs0 += __shfl_xor_sync(0xffffffffu, rs0, 1);
        rs0 += __shfl_xor_sync(0xffffffffu, rs0, 2);
        rs1 += __shfl_xor_sync(0xffffffffu, rs1, 1);
        rs1 += __shfl_xor_sync(0xffffffffu, rs1, 2);
        l0 = l0 * c0 + rs0;
        l1 = l1 * c1 + rs1;

#pragma unroll
        for (int ni = 0; ni < 8; ni++) {
            o[ni][0] *= c0; o[ni][1] *= c0;
            o[ni][2] *= c1; o[ni][3] *= c1;
        }

        // ---- O += P @ V over 64 keys
#pragma unroll
        for (int kc2 = 0; kc2 < 4; kc2++) {
            uint32_t af[4] = {ph[2 * kc2][0], ph[2 * kc2][1],
                              ph[2 * kc2 + 1][0], ph[2 * kc2 + 1][1]};
#pragma unroll
            for (int ni2 = 0; ni2 < 4; ni2++) {
                uint32_t va = (uint32_t)(
                    (kc2 * 16 + (q8 & 1) * 8 + l7) * FST
                    + ni2 * 16 + (q8 >> 1) * 8) * 2;
                uint32_t v4[4];
                LDSM_X4T(v4[0], v4[1], v4[2], v4[3], uV + va);
                mma16816h(o[ni2 * 2], af, v4);
                mma16816h(o[ni2 * 2 + 1], af, v4 + 2);
            }
        }
        __syncthreads();
    }

    // Epilogue
    float inv0 = 1.f / l0, inv1 = 1.f / l1;
    int r0 = q0 + wid * 16 + (lane >> 2);
    float* obase = outp + ((size_t)bb * S_ + r0) * DM_ + h * DH_;
#pragma unroll
    for (int ni = 0; ni < 8; ni++) {
        int col = ni * 8 + (lane & 3) * 2;
        float2 w0, w1;
        w0.x = o[ni][0] * inv0; w0.y = o[ni][1] * inv0;
        w1.x = o[ni][2] * inv1; w1.y = o[ni][3] * inv1;
        *(float2*)(obase + col) = w0;
        *(float2*)(obase + 8 * DM_ + col) = w1;
    }
}

// ---------------------------------------------------------------------------
extern "C" void kernel_launch(void* const* d_in, const int* in_sizes, int n_in,
                              void* d_out, int out_size)
{
    const float* x    = (const float*)d_in[0];
    const float* Wqkv = (const float*)d_in[1];
    const float* bqkv = (const float*)d_in[2];
    const float* Wout = (const float*)d_in[3];
    const float* bout = (const float*)d_in[4];
    float* out = (float*)d_out;

    float *qkv = nullptr, *attn = nullptr;
    __half* qkv16;
    __nv_bfloat16 *xh, *xl, *wqh, *wql, *woh, *wol, *ah, *al;
    cudaGetSymbolAddress((void**)&qkv, g_qkv);
    cudaGetSymbolAddress((void**)&attn, g_attn);
    cudaGetSymbolAddress((void**)&qkv16, g_qkv16);
    cudaGetSymbolAddress((void**)&xh, g_xh);
    cudaGetSymbolAddress((void**)&xl, g_xl);
    cudaGetSymbolAddress((void**)&wqh, g_wqh);
    cudaGetSymbolAddress((void**)&wql, g_wql);
    cudaGetSymbolAddress((void**)&woh, g_woh);
    cudaGetSymbolAddress((void**)&wol, g_wol);
    cudaGetSymbolAddress((void**)&ah, g_ah);
    cudaGetSymbolAddress((void**)&al, g_al);

    cudaFuncSetAttribute(gemm_mma_bf16x3,
                         cudaFuncAttributeMaxDynamicSharedMemorySize,
                         GEMM_SMEM_BYTES);
    cudaFuncSetAttribute(flash_h16, cudaFuncAttributeMaxDynamicSharedMemorySize,
                         FLASH_SMEM_BYTES);

    // 0) split inputs to bf16 hi/lo
    split_bf16<<<(M_ * DM_ / 4 + 255) / 256, 256>>>(x, xh, xl, M_ * DM_ / 4);
    split_bf16<<<(3 * DM_ * DM_ / 4 + 255) / 256, 256>>>(Wqkv, wqh, wql,
                                                         3 * DM_ * DM_ / 4);
    split_bf16<<<(DM_ * DM_ / 4 + 255) / 256, 256>>>(Wout, woh, wol,
                                                     DM_ * DM_ / 4);

    // 1) QKV projection (HMMA, bf16 3-pass, double-buffered)
    dim3 g1(3 * DM_ / 128, M_ / 128);
    gemm_mma_bf16x3<<<g1, 256, GEMM_SMEM_BYTES>>>(xh, xl, wqh, wql, bqkv, qkv,
                                                  M_, 3 * DM_, DM_);

    // 2) RoPE + fp16 convert (q pre-scaled by 1/8)
    rope_h16<<<(M_ * (ROWSTRIDE / 2)) / 256, 256>>>(qkv, qkv16);

    // 3) Flash attention (fp16 single-pass HMMA)
    dim3 g3(S_ / 128, B_ * H_);
    flash_h16<<<g3, 256, FLASH_SMEM_BYTES>>>(qkv16, attn);

    // 4) split attention output, then out projection (bf16 3-pass)
    split_bf16<<<(M_ * DM_ / 4 + 255) / 256, 256>>>(attn, ah, al, M_ * DM_ / 4);
    dim3 g4(DM_ / 128, M_ / 128);
    gemm_mma_bf16x3<<<g4, 256, GEMM_SMEM_BYTES>>>(ah, al, woh, wol, bout, out,
                                                  M_, DM_, DM_);
}

// round 7
// speedup vs baseline: 4.2687x; 2.3703x over previous
#include <cuda_runtime.h>
#include <cuda_bf16.h>
#include <cuda_fp16.h>
#include <math.h>
#include <stdint.h>

// Problem constants
#define B_   2
#define S_   2048
#define DM_  1024
#define H_   16
#define DH_  64
#define M_   (B_ * S_)          // 4096 rows
#define ROWSTRIDE 3072          // qkv row stride (3*DM_)

// Scratch (allocation-free rule: __device__ globals)
__device__ __half g_qkv16[(size_t)M_ * 3 * DM_];
__device__ __nv_bfloat16 g_xh[(size_t)M_ * DM_];
__device__ __nv_bfloat16 g_xl[(size_t)M_ * DM_];
__device__ __nv_bfloat16 g_wqh[(size_t)3 * DM_ * DM_];
__device__ __nv_bfloat16 g_wql[(size_t)3 * DM_ * DM_];
__device__ __nv_bfloat16 g_woh[(size_t)DM_ * DM_];
__device__ __nv_bfloat16 g_wol[(size_t)DM_ * DM_];
__device__ __nv_bfloat16 g_ah[(size_t)M_ * DM_];
__device__ __nv_bfloat16 g_al[(size_t)M_ * DM_];

// Correctly-rounded fp32 inv_freq table: 10000^(-p/16) = 10^(-p/4)
__constant__ float c_invf[16] = {
    1.0f,                    5.623413251903491e-01f,
    3.1622776601683794e-01f, 1.7782794100389228e-01f,
    1.0e-01f,                5.623413251903491e-02f,
    3.1622776601683794e-02f, 1.7782794100389228e-02f,
    1.0e-02f,                5.623413251903491e-03f,
    3.1622776601683794e-03f, 1.7782794100389228e-03f,
    1.0e-03f,                5.623413251903491e-04f,
    3.1622776601683794e-04f, 1.7782794100389228e-04f
};

// ---------------------------------------------------------------------------
// PTX helpers
// ---------------------------------------------------------------------------
__device__ __forceinline__ uint32_t smem_u32(const void* p) {
    uint32_t a;
    asm("{ .reg .u64 t; cvta.to.shared.u64 t, %1; cvt.u32.u64 %0, t; }"
        : "=r"(a) : "l"(p));
    return a;
}

#define LDSM_X4(r0, r1, r2, r3, addr) \
    asm volatile("ldmatrix.sync.aligned.m8n8.x4.shared.b16 {%0,%1,%2,%3}, [%4];" \
                 : "=r"(r0), "=r"(r1), "=r"(r2), "=r"(r3) : "r"(addr))
#define LDSM_X4T(r0, r1, r2, r3, addr) \
    asm volatile("ldmatrix.sync.aligned.m8n8.x4.trans.shared.b16 {%0,%1,%2,%3}, [%4];" \
                 : "=r"(r0), "=r"(r1), "=r"(r2), "=r"(r3) : "r"(addr))
#define LDSM_X2(r0, r1, addr) \
    asm volatile("ldmatrix.sync.aligned.m8n8.x2.shared.b16 {%0,%1}, [%2];" \
                 : "=r"(r0), "=r"(r1) : "r"(addr))

#define CP_ASYNC16(dst, src) \
    asm volatile("cp.async.cg.shared.global [%0], [%1], 16;" \
                 :: "r"(dst), "l"(src))
#define CP_COMMIT() asm volatile("cp.async.commit_group;" ::: "memory")
#define CP_WAIT(n)  asm volatile("cp.async.wait_group %0;" :: "n"(n) : "memory")

// bf16 mma (projections)
__device__ __forceinline__ void mma16816(float* c, const uint32_t* a,
                                         const uint32_t* b) {
    asm volatile(
        "mma.sync.aligned.m16n8k16.row.col.f32.bf16.bf16.f32 "
        "{%0,%1,%2,%3}, {%4,%5,%6,%7}, {%8,%9}, {%0,%1,%2,%3};"
        : "+f"(c[0]), "+f"(c[1]), "+f"(c[2]), "+f"(c[3])
        : "r"(a[0]), "r"(a[1]), "r"(a[2]), "r"(a[3]), "r"(b[0]), "r"(b[1]));
}
// fp16 mma (attention)
__device__ __forceinline__ void mma16816h(float* c, const uint32_t* a,
                                          const uint32_t* b) {
    asm volatile(
        "mma.sync.aligned.m16n8k16.row.col.f32.f16.f16.f32 "
        "{%0,%1,%2,%3}, {%4,%5,%6,%7}, {%8,%9}, {%0,%1,%2,%3};"
        : "+f"(c[0]), "+f"(c[1]), "+f"(c[2]), "+f"(c[3])
        : "r"(a[0]), "r"(a[1]), "r"(a[2]), "r"(a[3]), "r"(b[0]), "r"(b[1]));
}

__device__ __forceinline__ uint32_t packh(float a, float b) {
    __half2 t = __float22half2_rn(make_float2(a, b));
    return *(uint32_t*)&t;
}

// ---------------------------------------------------------------------------
// split: fp32 -> bf16 hi + bf16 lo
// ---------------------------------------------------------------------------
__global__ __launch_bounds__(256) void split_bf16(
    const float* __restrict__ src, __nv_bfloat16* __restrict__ hi,
    __nv_bfloat16* __restrict__ lo, int n4)
{
    int i = blockIdx.x * blockDim.x + threadIdx.x;
    if (i >= n4) return;
    float4 v = ((const float4*)src)[i];
    __nv_bfloat162 h0 = __float22bfloat162_rn(make_float2(v.x, v.y));
    __nv_bfloat162 h1 = __float22bfloat162_rn(make_float2(v.z, v.w));
    float2 b0 = __bfloat1622float2(h0);
    float2 b1 = __bfloat1622float2(h1);
    __nv_bfloat162 l0 = __float22bfloat162_rn(make_float2(v.x - b0.x, v.y - b0.y));
    __nv_bfloat162 l1 = __float22bfloat162_rn(make_float2(v.z - b1.x, v.w - b1.y));
    uint2 hp, lp;
    hp.x = *(uint32_t*)&h0; hp.y = *(uint32_t*)&h1;
    lp.x = *(uint32_t*)&l0; lp.y = *(uint32_t*)&l1;
    ((uint2*)hi)[i] = hp;
    ((uint2*)lo)[i] = lp;
}

// ---------------------------------------------------------------------------
// Apply RoPE (fp32) to one bias-added value pair at (row, col even).
// Returns the rotated (and q-scaled) pair ready for fp16 conversion.
// ---------------------------------------------------------------------------
__device__ __forceinline__ float2 rope_pair(float2 v, int row, int col) {
    int hd = col & 63;
    int sec = col >> 10;                 // 0=q 1=k 2=v
    if (sec < 2 && hd < 32) {
        float inv_freq = c_invf[hd >> 1];
        float sn, cs;
        sincosf((float)(row & (S_ - 1)) * inv_freq, &sn, &cs);
        float x1 = v.x, x2 = v.y;
        v.x = x1 * cs - x2 * sn;
        v.y = x2 * cs + x1 * sn;
    }
    if (sec == 0) { v.x *= 0.125f; v.y *= 0.125f; }
    return v;
}

// ---------------------------------------------------------------------------
// HMMA GEMM, split-bf16 3-pass, cp.async double-buffered.
// Epilogue: if C16 != nullptr -> bias + RoPE + fp16 store (QKV path);
//           else              -> bias + fp32 store   (out-proj path).
// ---------------------------------------------------------------------------
#define BK 32
#define ASTR 40
#define STG_H (128 * ASTR)
#define GEMM_SMEM_BYTES (2 * 4 * STG_H * 2)

__global__ __launch_bounds__(256) void gemm_mma_bf16x3(
    const __nv_bfloat16* __restrict__ Ah, const __nv_bfloat16* __restrict__ Al,
    const __nv_bfloat16* __restrict__ Bh, const __nv_bfloat16* __restrict__ Bl,
    const float* __restrict__ bias, float* __restrict__ C,
    __half* __restrict__ C16, int M, int N, int K)
{
    extern __shared__ __nv_bfloat16 gsm[];
    const uint32_t uG = smem_u32(gsm);

    const int tid = threadIdx.x;
    const int wid = tid >> 5;
    const int lane = tid & 31;
    const int warp_m = wid & 1;
    const int warp_n = wid >> 1;
    const int bm = blockIdx.y * 128;
    const int bn = blockIdx.x * 128;

    const __nv_bfloat16* src[4];
    src[0] = Ah + (size_t)bm * K;
    src[1] = Al + (size_t)bm * K;
    src[2] = Bh + (size_t)bn * K;
    src[3] = Bl + (size_t)bn * K;

    float acc[4][4][4];
#pragma unroll
    for (int i = 0; i < 4; i++)
#pragma unroll
        for (int j = 0; j < 4; j++)
#pragma unroll
            for (int e = 0; e < 4; e++) acc[i][j][e] = 0.f;

    const int niter = K / BK;
    {
#pragma unroll
        for (int i = 0; i < 2; i++) {
            int L = i * 256 + tid;
            int r = L >> 2, c8 = (L & 3) * 8;
            size_t g = (size_t)r * K + c8;
#pragma unroll
            for (int t4 = 0; t4 < 4; t4++) {
                uint32_t d = uG + (uint32_t)(t4 * STG_H + r * ASTR + c8) * 2;
                CP_ASYNC16(d, src[t4] + g);
            }
        }
        CP_COMMIT();
    }

    for (int it = 0; it < niter; it++) {
        const int stage = it & 1;
        if (it + 1 < niter) {
            const int k0 = (it + 1) * BK;
            const uint32_t sbase = (uint32_t)((stage ^ 1) * 4 * STG_H) * 2;
#pragma unroll
            for (int i = 0; i < 2; i++) {
                int L = i * 256 + tid;
                int r = L >> 2, c8 = (L & 3) * 8;
                size_t g = (size_t)r * K + k0 + c8;
#pragma unroll
                for (int t4 = 0; t4 < 4; t4++) {
                    uint32_t d = uG + sbase + (uint32_t)(t4 * STG_H + r * ASTR + c8) * 2;
                    CP_ASYNC16(d, src[t4] + g);
                }
            }
            CP_COMMIT();
            CP_WAIT(1);
        } else {
            CP_WAIT(0);
        }
        __syncthreads();

        const uint32_t uAh = uG + (uint32_t)(stage * 4 * STG_H) * 2;
        const uint32_t uAl = uAh + STG_H * 2;
        const uint32_t uBh = uAl + STG_H * 2;
        const uint32_t uBl = uBh + STG_H * 2;

#pragma unroll
        for (int ks = 0; ks < 2; ks++) {
            uint32_t ah[4][4], al[4][4], bh[4][2], bl[4][2];
            const int kof = ks * 16 + (lane >> 4) * 8;
            const int kofb = ks * 16 + ((lane >> 3) & 1) * 8;
#pragma unroll
            for (int mi = 0; mi < 4; mi++) {
                uint32_t r = (uint32_t)((warp_m * 64 + mi * 16 + (lane & 15)) * ASTR + kof) * 2;
                LDSM_X4(ah[mi][0], ah[mi][1], ah[mi][2], ah[mi][3], uAh + r);
                LDSM_X4(al[mi][0], al[mi][1], al[mi][2], al[mi][3], uAl + r);
            }
#pragma unroll
            for (int ni = 0; ni < 4; ni++) {
                uint32_t r = (uint32_t)((warp_n * 32 + ni * 8 + (lane & 7)) * ASTR + kofb) * 2;
                LDSM_X2(bh[ni][0], bh[ni][1], uBh + r);
                LDSM_X2(bl[ni][0], bl[ni][1], uBl + r);
            }
#pragma unroll
            for (int mi = 0; mi < 4; mi++)
#pragma unroll
                for (int ni = 0; ni < 4; ni++) {
                    mma16816(acc[mi][ni], ah[mi], bh[ni]);
                    mma16816(acc[mi][ni], ah[mi], bl[ni]);
                    mma16816(acc[mi][ni], al[mi], bh[ni]);
                }
        }
        __syncthreads();
    }

    const int m0 = bm + warp_m * 64;
    const int n0 = bn + warp_n * 32;
#pragma unroll
    for (int mi = 0; mi < 4; mi++) {
#pragma unroll
        for (int ni = 0; ni < 4; ni++) {
            int col = n0 + ni * 8 + (lane & 3) * 2;
            float2 bv = *(const float2*)(bias + col);
            int r0 = m0 + mi * 16 + (lane >> 2);
            float2 o0, o1;
            o0.x = acc[mi][ni][0] + bv.x;
            o0.y = acc[mi][ni][1] + bv.y;
            o1.x = acc[mi][ni][2] + bv.x;
            o1.y = acc[mi][ni][3] + bv.y;
            if (C16) {
                o0 = rope_pair(o0, r0, col);
                o1 = rope_pair(o1, r0 + 8, col);
                *(__half2*)(C16 + (size_t)r0 * N + col) = __float22half2_rn(o0);
                *(__half2*)(C16 + (size_t)(r0 + 8) * N + col) = __float22half2_rn(o1);
            } else {
                *(float2*)(C + (size_t)r0 * N + col) = o0;
                *(float2*)(C + (size_t)(r0 + 8) * N + col) = o1;
            }
        }
    }
}

// ---------------------------------------------------------------------------
// Flash attention, single-pass fp16 HMMA; Q fragments register-resident;
// K/V double-buffered via cp.async. Epilogue writes bf16 hi/lo directly.
// ---------------------------------------------------------------------------
#define FST 72
#define KVT (64 * FST)
#define FLASH_SMEM_BYTES (2 * 2 * KVT * 2)

__global__ __launch_bounds__(256, 2) void flash_h16(
    const __half* __restrict__ qkv16,
    __nv_bfloat16* __restrict__ oh, __nv_bfloat16* __restrict__ ol)
{
    extern __shared__ __half hsm[];
    const uint32_t uF = smem_u32(hsm);

    const int tid = threadIdx.x;
    const int wid = tid >> 5, lane = tid & 31;
    const int bhid = blockIdx.y;
    const int bb = bhid >> 4, h = bhid & 15;
    const int q0 = blockIdx.x * 128;

    const size_t rowbase = (size_t)bb * S_ * ROWSTRIDE;
    const __half* qb = qkv16 + rowbase + h * DH_;
    const __half* kb = qb + DM_;
    const __half* vb = qb + 2 * DM_;

    // Stage Q (128 x 64 halfs) into smem, lift fragments to registers
#pragma unroll
    for (int it = 0; it < 4; it++) {
        int L = it * 256 + tid;
        int r = L >> 3, c8 = (L & 7) * 8;
        size_t g = (size_t)(q0 + r) * ROWSTRIDE + c8;
        *(uint4*)(hsm + r * FST + c8) = *(const uint4*)(qb + g);
    }
    __syncthreads();

    uint32_t qf[4][4];
#pragma unroll
    for (int kc = 0; kc < 4; kc++) {
        uint32_t qa = (uint32_t)((wid * 16 + (lane & 15)) * FST + kc * 16
                                 + 8 * (lane >> 4)) * 2;
        LDSM_X4(qf[kc][0], qf[kc][1], qf[kc][2], qf[kc][3], uF + qa);
    }
    __syncthreads();

    float o[8][4];
#pragma unroll
    for (int ni = 0; ni < 8; ni++)
#pragma unroll
        for (int e = 0; e < 4; e++) o[ni][e] = 0.f;
    float m0 = -INFINITY, m1 = -INFINITY, l0 = 0.f, l1 = 0.f;

    const int q8 = lane >> 3;
    const int l7 = lane & 7;

    {
#pragma unroll
        for (int it = 0; it < 4; it++) {
            int L = it * 256 + tid;
            int tsel = L >> 9;
            int r = (L >> 3) & 63, c8 = (L & 7) * 8;
            const __half* srcp = (tsel == 0 ? kb : vb)
                                 + (size_t)r * ROWSTRIDE + c8;
            uint32_t d = uF + (uint32_t)(tsel * KVT + r * FST + c8) * 2;
            CP_ASYNC16(d, srcp);
        }
        CP_COMMIT();
    }

    for (int t = 0; t < S_ / 64; t++) {
        const int st = t & 1;
        if (t + 1 < S_ / 64) {
            const uint32_t sbase = (uint32_t)((st ^ 1) * 2 * KVT) * 2;
#pragma unroll
            for (int it = 0; it < 4; it++) {
                int L = it * 256 + tid;
                int tsel = L >> 9;
                int r = (L >> 3) & 63, c8 = (L & 7) * 8;
                const __half* srcp = (tsel == 0 ? kb : vb)
                                     + (size_t)((t + 1) * 64 + r) * ROWSTRIDE + c8;
                uint32_t d = uF + sbase + (uint32_t)(tsel * KVT + r * FST + c8) * 2;
                CP_ASYNC16(d, srcp);
            }
            CP_COMMIT();
            CP_WAIT(1);
        } else {
            CP_WAIT(0);
        }
        __syncthreads();

        const uint32_t uK = uF + (uint32_t)(st * 2 * KVT) * 2;
        const uint32_t uV = uK + (uint32_t)KVT * 2;

        // S = Q @ K^T over 64 keys
        float s[8][4];
#pragma unroll
        for (int ni = 0; ni < 8; ni++)
#pragma unroll
            for (int e = 0; e < 4; e++) s[ni][e] = 0.f;

#pragma unroll
        for (int kc = 0; kc < 4; kc++) {
#pragma unroll
            for (int ni2 = 0; ni2 < 4; ni2++) {
                uint32_t ka = (uint32_t)(
                    (ni2 * 16 + (q8 >> 1) * 8 + l7) * FST
                    + kc * 16 + (q8 & 1) * 8) * 2;
                uint32_t k4[4];
                LDSM_X4(k4[0], k4[1], k4[2], k4[3], uK + ka);
                mma16816h(s[ni2 * 2], qf[kc], k4);
                mma16816h(s[ni2 * 2 + 1], qf[kc], k4 + 2);
            }
        }

        // Online softmax
        float rm0 = -INFINITY, rm1 = -INFINITY;
#pragma unroll
        for (int ni = 0; ni < 8; ni++) {
            rm0 = fmaxf(rm0, fmaxf(s[ni][0], s[ni][1]));
            rm1 = fmaxf(rm1, fmaxf(s[ni][2], s[ni][3]));
        }
        rm0 = fmaxf(rm0, __shfl_xor_sync(0xffffffffu, rm0, 1));
        rm0 = fmaxf(rm0, __shfl_xor_sync(0xffffffffu, rm0, 2));
        rm1 = fmaxf(rm1, __shfl_xor_sync(0xffffffffu, rm1, 1));
        rm1 = fmaxf(rm1, __shfl_xor_sync(0xffffffffu, rm1, 2));

        float mn0 = fmaxf(m0, rm0), mn1 = fmaxf(m1, rm1);
        float c0 = __expf(m0 - mn0), c1 = __expf(m1 - mn1);
        m0 = mn0; m1 = mn1;

        float rs0 = 0.f, rs1 = 0.f;
        uint32_t ph[8][2];
#pragma unroll
        for (int ni = 0; ni < 8; ni++) {
            s[ni][0] = __expf(s[ni][0] - mn0);
            s[ni][1] = __expf(s[ni][1] - mn0);
            s[ni][2] = __expf(s[ni][2] - mn1);
            s[ni][3] = __expf(s[ni][3] - mn1);
            rs0 += s[ni][0] + s[ni][1];
            rs1 += s[ni][2] + s[ni][3];
            ph[ni][0] = packh(s[ni][0], s[ni][1]);
            ph[ni][1] = packh(s[ni][2], s[ni][3]);
        }
        rs0 += __shfl_xor_sync(0xffffffffu, rs0, 1);
        rs0 += __shfl_xor_sync(0xffffffffu, rs0, 2);
        rs1 += __shfl_xor_sync(0xffffffffu, rs1, 1);
        rs1 += __shfl_xor_sync(0xffffffffu, rs1, 2);
        l0 = l0 * c0 + rs0;
        l1 = l1 * c1 + rs1;

#pragma unroll
        for (int ni = 0; ni < 8; ni++) {
            o[ni][0] *= c0; o[ni][1] *= c0;
            o[ni][2] *= c1; o[ni][3] *= c1;
        }

        // O += P @ V over 64 keys
#pragma unroll
        for (int kc2 = 0; kc2 < 4; kc2++) {
            uint32_t af[4] = {ph[2 * kc2][0], ph[2 * kc2][1],
                              ph[2 * kc2 + 1][0], ph[2 * kc2 + 1][1]};
#pragma unroll
            for (int ni2 = 0; ni2 < 4; ni2++) {
                uint32_t va = (uint32_t)(
                    (kc2 * 16 + (q8 & 1) * 8 + l7) * FST
                    + ni2 * 16 + (q8 >> 1) * 8) * 2;
                uint32_t v4[4];
                LDSM_X4T(v4[0], v4[1], v4[2], v4[3], uV + va);
                mma16816h(o[ni2 * 2], af, v4);
                mma16816h(o[ni2 * 2 + 1], af, v4 + 2);
            }
        }
        __syncthreads();
    }

    // Epilogue: normalize, split to bf16 hi/lo, store
    float inv0 = 1.f / l0, inv1 = 1.f / l1;
    int r0 = q0 + wid * 16 + (lane >> 2);
    size_t obase = ((size_t)bb * S_ + r0) * DM_ + h * DH_;
#pragma unroll
    for (int ni = 0; ni < 8; ni++) {
        int col = ni * 8 + (lane & 3) * 2;
        float2 w0, w1;
        w0.x = o[ni][0] * inv0; w0.y = o[ni][1] * inv0;
        w1.x = o[ni][2] * inv1; w1.y = o[ni][3] * inv1;
        __nv_bfloat162 h0 = __float22bfloat162_rn(w0);
        __nv_bfloat162 h1 = __float22bfloat162_rn(w1);
        float2 b0 = __bfloat1622float2(h0);
        float2 b1 = __bfloat1622float2(h1);
        __nv_bfloat162 e0 = __float22bfloat162_rn(make_float2(w0.x - b0.x, w0.y - b0.y));
        __nv_bfloat162 e1 = __float22bfloat162_rn(make_float2(w1.x - b1.x, w1.y - b1.y));
        *(__nv_bfloat162*)(oh + obase + col) = h0;
        *(__nv_bfloat162*)(ol + obase + col) = e0;
        *(__nv_bfloat162*)(oh + obase + 8 * DM_ + col) = h1;
        *(__nv_bfloat162*)(ol + obase + 8 * DM_ + col) = e1;
    }
}

// ---------------------------------------------------------------------------
extern "C" void kernel_launch(void* const* d_in, const int* in_sizes, int n_in,
                              void* d_out, int out_size)
{
    const float* x    = (const float*)d_in[0];
    const float* Wqkv = (const float*)d_in[1];
    const float* bqkv = (const float*)d_in[2];
    const float* Wout = (const float*)d_in[3];
    const float* bout = (const float*)d_in[4];
    float* out = (float*)d_out;

    __half* qkv16;
    __nv_bfloat16 *xh, *xl, *wqh, *wql, *woh, *wol, *ah, *al;
    cudaGetSymbolAddress((void**)&qkv16, g_qkv16);
    cudaGetSymbolAddress((void**)&xh, g_xh);
    cudaGetSymbolAddress((void**)&xl, g_xl);
    cudaGetSymbolAddress((void**)&wqh, g_wqh);
    cudaGetSymbolAddress((void**)&wql, g_wql);
    cudaGetSymbolAddress((void**)&woh, g_woh);
    cudaGetSymbolAddress((void**)&wol, g_wol);
    cudaGetSymbolAddress((void**)&ah, g_ah);
    cudaGetSymbolAddress((void**)&al, g_al);

    cudaFuncSetAttribute(gemm_mma_bf16x3,
                         cudaFuncAttributeMaxDynamicSharedMemorySize,
                         GEMM_SMEM_BYTES);
    cudaFuncSetAttribute(flash_h16, cudaFuncAttributeMaxDynamicSharedMemorySize,
                         FLASH_SMEM_BYTES);

    // 0) split inputs to bf16 hi/lo
    split_bf16<<<(M_ * DM_ / 4 + 255) / 256, 256>>>(x, xh, xl, M_ * DM_ / 4);
    split_bf16<<<(3 * DM_ * DM_ / 4 + 255) / 256, 256>>>(Wqkv, wqh, wql,
                                                         3 * DM_ * DM_ / 4);
    split_bf16<<<(DM_ * DM_ / 4 + 255) / 256, 256>>>(Wout, woh, wol,
                                                     DM_ * DM_ / 4);

    // 1) QKV projection + fused bias + RoPE + fp16 convert
    dim3 g1(3 * DM_ / 128, M_ / 128);
    gemm_mma_bf16x3<<<g1, 256, GEMM_SMEM_BYTES>>>(xh, xl, wqh, wql, bqkv,
                                                  nullptr, qkv16,
                                                  M_, 3 * DM_, DM_);

    // 2) Flash attention (fp16 single-pass), writes bf16 hi/lo directly
    dim3 g3(S_ / 128, B_ * H_);
    flash_h16<<<g3, 256, FLASH_SMEM_BYTES>>>(qkv16, ah, al);

    // 3) Out projection (bf16 3-pass), fp32 output + bias
    dim3 g4(DM_ / 128, M_ / 128);
    gemm_mma_bf16x3<<<g4, 256, GEMM_SMEM_BYTES>>>(ah, al, woh, wol, bout,
                                                  out, nullptr,
                                                  M_, DM_, DM_);
}

// round 8
// speedup vs baseline: 6.5814x; 1.5418x over previous
#include <cuda_runtime.h>
#include <cuda_fp16.h>
#include <math.h>
#include <stdint.h>

// Problem constants
#define B_   2
#define S_   2048
#define DM_  1024
#define H_   16
#define DH_  64
#define M_   (B_ * S_)          // 4096 rows
#define ROWSTRIDE 3072          // qkv row stride (3*DM_)

// Scratch (allocation-free rule: __device__ globals)
__device__ __half g_qkv16[(size_t)M_ * 3 * DM_];
__device__ __half g_x16[(size_t)M_ * DM_];
__device__ __half g_wq16[(size_t)3 * DM_ * DM_];
__device__ __half g_wo16[(size_t)DM_ * DM_];
__device__ __half g_attn16[(size_t)M_ * DM_];

// Correctly-rounded fp32 inv_freq table: 10000^(-p/16) = 10^(-p/4)
__constant__ float c_invf[16] = {
    1.0f,                    5.623413251903491e-01f,
    3.1622776601683794e-01f, 1.7782794100389228e-01f,
    1.0e-01f,                5.623413251903491e-02f,
    3.1622776601683794e-02f, 1.7782794100389228e-02f,
    1.0e-02f,                5.623413251903491e-03f,
    3.1622776601683794e-03f, 1.7782794100389228e-03f,
    1.0e-03f,                5.623413251903491e-04f,
    3.1622776601683794e-04f, 1.7782794100389228e-04f
};

// ---------------------------------------------------------------------------
// PTX helpers
// ---------------------------------------------------------------------------
__device__ __forceinline__ uint32_t smem_u32(const void* p) {
    uint32_t a;
    asm("{ .reg .u64 t; cvta.to.shared.u64 t, %1; cvt.u32.u64 %0, t; }"
        : "=r"(a) : "l"(p));
    return a;
}

#define LDSM_X4(r0, r1, r2, r3, addr) \
    asm volatile("ldmatrix.sync.aligned.m8n8.x4.shared.b16 {%0,%1,%2,%3}, [%4];" \
                 : "=r"(r0), "=r"(r1), "=r"(r2), "=r"(r3) : "r"(addr))
#define LDSM_X4T(r0, r1, r2, r3, addr) \
    asm volatile("ldmatrix.sync.aligned.m8n8.x4.trans.shared.b16 {%0,%1,%2,%3}, [%4];" \
                 : "=r"(r0), "=r"(r1), "=r"(r2), "=r"(r3) : "r"(addr))
#define LDSM_X2(r0, r1, addr) \
    asm volatile("ldmatrix.sync.aligned.m8n8.x2.shared.b16 {%0,%1}, [%2];" \
                 : "=r"(r0), "=r"(r1) : "r"(addr))

#define CP_ASYNC16(dst, src) \
    asm volatile("cp.async.cg.shared.global [%0], [%1], 16;" \
                 :: "r"(dst), "l"(src))
#define CP_COMMIT() asm volatile("cp.async.commit_group;" ::: "memory")
#define CP_WAIT(n)  asm volatile("cp.async.wait_group %0;" :: "n"(n) : "memory")

// fp16 mma
__device__ __forceinline__ void mma16816h(float* c, const uint32_t* a,
                                          const uint32_t* b) {
    asm volatile(
        "mma.sync.aligned.m16n8k16.row.col.f32.f16.f16.f32 "
        "{%0,%1,%2,%3}, {%4,%5,%6,%7}, {%8,%9}, {%0,%1,%2,%3};"
        : "+f"(c[0]), "+f"(c[1]), "+f"(c[2]), "+f"(c[3])
        : "r"(a[0]), "r"(a[1]), "r"(a[2]), "r"(a[3]), "r"(b[0]), "r"(b[1]));
}

__device__ __forceinline__ uint32_t packh(float a, float b) {
    __half2 t = __float22half2_rn(make_float2(a, b));
    return *(uint32_t*)&t;
}

// ---------------------------------------------------------------------------
// convert: fp32 -> fp16
// ---------------------------------------------------------------------------
__global__ __launch_bounds__(256) void convert_h16(
    const float* __restrict__ src, __half* __restrict__ dst, int n4)
{
    int i = blockIdx.x * blockDim.x + threadIdx.x;
    if (i >= n4) return;
    float4 v = ((const float4*)src)[i];
    __half2 h0 = __float22half2_rn(make_float2(v.x, v.y));
    __half2 h1 = __float22half2_rn(make_float2(v.z, v.w));
    uint2 hp;
    hp.x = *(uint32_t*)&h0; hp.y = *(uint32_t*)&h1;
    ((uint2*)dst)[i] = hp;
}

// ---------------------------------------------------------------------------
// Apply RoPE (fp32) to one bias-added value pair at (row, col even).
// ---------------------------------------------------------------------------
__device__ __forceinline__ float2 rope_pair(float2 v, int row, int col) {
    int hd = col & 63;
    int sec = col >> 10;                 // 0=q 1=k 2=v
    if (sec < 2 && hd < 32) {
        float inv_freq = c_invf[hd >> 1];
        float sn, cs;
        sincosf((float)(row & (S_ - 1)) * inv_freq, &sn, &cs);
        float x1 = v.x, x2 = v.y;
        v.x = x1 * cs - x2 * sn;
        v.y = x2 * cs + x1 * sn;
    }
    if (sec == 0) { v.x *= 0.125f; v.y *= 0.125f; }
    return v;
}

// ---------------------------------------------------------------------------
// HMMA GEMM, single-pass fp16, cp.async double-buffered.
// C[M,N] = A[M,K] @ W[N,K]^T + bias.
// Epilogue: C16 != nullptr -> bias + RoPE + fp16 (QKV); else fp32 + bias.
// ---------------------------------------------------------------------------
#define BK 32
#define ASTR 40
#define STG_H (128 * ASTR)
#define GEMM_SMEM_BYTES (2 * 2 * STG_H * 2)   // 40960

__global__ __launch_bounds__(256) void gemm_mma_h16(
    const __half* __restrict__ A, const __half* __restrict__ Bm,
    const float* __restrict__ bias, float* __restrict__ C,
    __half* __restrict__ C16, int M, int N, int K)
{
    extern __shared__ __half gsm[];
    const uint32_t uG = smem_u32(gsm);

    const int tid = threadIdx.x;
    const int wid = tid >> 5;
    const int lane = tid & 31;
    const int warp_m = wid & 1;
    const int warp_n = wid >> 1;
    const int bm = blockIdx.y * 128;
    const int bn = blockIdx.x * 128;

    const __half* srcA = A + (size_t)bm * K;
    const __half* srcB = Bm + (size_t)bn * K;

    float acc[4][4][4];
#pragma unroll
    for (int i = 0; i < 4; i++)
#pragma unroll
        for (int j = 0; j < 4; j++)
#pragma unroll
            for (int e = 0; e < 4; e++) acc[i][j][e] = 0.f;

    const int niter = K / BK;
    {
#pragma unroll
        for (int i = 0; i < 2; i++) {
            int L = i * 256 + tid;
            int r = L >> 2, c8 = (L & 3) * 8;
            size_t g = (size_t)r * K + c8;
            uint32_t dA = uG + (uint32_t)(r * ASTR + c8) * 2;
            uint32_t dB = uG + (uint32_t)(STG_H + r * ASTR + c8) * 2;
            CP_ASYNC16(dA, srcA + g);
            CP_ASYNC16(dB, srcB + g);
        }
        CP_COMMIT();
    }

    for (int it = 0; it < niter; it++) {
        const int stage = it & 1;
        if (it + 1 < niter) {
            const int k0 = (it + 1) * BK;
            const uint32_t sbase = (uint32_t)((stage ^ 1) * 2 * STG_H) * 2;
#pragma unroll
            for (int i = 0; i < 2; i++) {
                int L = i * 256 + tid;
                int r = L >> 2, c8 = (L & 3) * 8;
                size_t g = (size_t)r * K + k0 + c8;
                uint32_t dA = uG + sbase + (uint32_t)(r * ASTR + c8) * 2;
                uint32_t dB = uG + sbase + (uint32_t)(STG_H + r * ASTR + c8) * 2;
                CP_ASYNC16(dA, srcA + g);
                CP_ASYNC16(dB, srcB + g);
            }
            CP_COMMIT();
            CP_WAIT(1);
        } else {
            CP_WAIT(0);
        }
        __syncthreads();

        const uint32_t uA = uG + (uint32_t)(stage * 2 * STG_H) * 2;
        const uint32_t uB = uA + STG_H * 2;

#pragma unroll
        for (int ks = 0; ks < 2; ks++) {
            uint32_t af[4][4], bf[4][2];
            const int kof = ks * 16 + (lane >> 4) * 8;
            const int kofb = ks * 16 + ((lane >> 3) & 1) * 8;
#pragma unroll
            for (int mi = 0; mi < 4; mi++) {
                uint32_t r = (uint32_t)((warp_m * 64 + mi * 16 + (lane & 15)) * ASTR + kof) * 2;
                LDSM_X4(af[mi][0], af[mi][1], af[mi][2], af[mi][3], uA + r);
            }
#pragma unroll
            for (int ni = 0; ni < 4; ni++) {
                uint32_t r = (uint32_t)((warp_n * 32 + ni * 8 + (lane & 7)) * ASTR + kofb) * 2;
                LDSM_X2(bf[ni][0], bf[ni][1], uB + r);
            }
#pragma unroll
            for (int mi = 0; mi < 4; mi++)
#pragma unroll
                for (int ni = 0; ni < 4; ni++)
                    mma16816h(acc[mi][ni], af[mi], bf[ni]);
        }
        __syncthreads();
    }

    const int m0 = bm + warp_m * 64;
    const int n0 = bn + warp_n * 32;
#pragma unroll
    for (int mi = 0; mi < 4; mi++) {
#pragma unroll
        for (int ni = 0; ni < 4; ni++) {
            int col = n0 + ni * 8 + (lane & 3) * 2;
            float2 bv = *(const float2*)(bias + col);
            int r0 = m0 + mi * 16 + (lane >> 2);
            float2 o0, o1;
            o0.x = acc[mi][ni][0] + bv.x;
            o0.y = acc[mi][ni][1] + bv.y;
            o1.x = acc[mi][ni][2] + bv.x;
            o1.y = acc[mi][ni][3] + bv.y;
            if (C16) {
                o0 = rope_pair(o0, r0, col);
                o1 = rope_pair(o1, r0 + 8, col);
                *(__half2*)(C16 + (size_t)r0 * N + col) = __float22half2_rn(o0);
                *(__half2*)(C16 + (size_t)(r0 + 8) * N + col) = __float22half2_rn(o1);
            } else {
                *(float2*)(C + (size_t)r0 * N + col) = o0;
                *(float2*)(C + (size_t)(r0 + 8) * N + col) = o1;
            }
        }
    }
}

// ---------------------------------------------------------------------------
// Flash attention, single-pass fp16 HMMA; Q fragments register-resident;
// K/V double-buffered via cp.async. Epilogue writes fp16 directly.
// ---------------------------------------------------------------------------
#define FST 72
#define KVT (64 * FST)
#define FLASH_SMEM_BYTES (2 * 2 * KVT * 2)

__global__ __launch_bounds__(256, 2) void flash_h16(
    const __half* __restrict__ qkv16, __half* __restrict__ attn16)
{
    extern __shared__ __half hsm[];
    const uint32_t uF = smem_u32(hsm);

    const int tid = threadIdx.x;
    const int wid = tid >> 5, lane = tid & 31;
    const int bhid = blockIdx.y;
    const int bb = bhid >> 4, h = bhid & 15;
    const int q0 = blockIdx.x * 128;

    const size_t rowbase = (size_t)bb * S_ * ROWSTRIDE;
    const __half* qb = qkv16 + rowbase + h * DH_;
    const __half* kb = qb + DM_;
    const __half* vb = qb + 2 * DM_;

    // Stage Q into smem, lift fragments to registers
#pragma unroll
    for (int it = 0; it < 4; it++) {
        int L = it * 256 + tid;
        int r = L >> 3, c8 = (L & 7) * 8;
        size_t g = (size_t)(q0 + r) * ROWSTRIDE + c8;
        *(uint4*)(hsm + r * FST + c8) = *(const uint4*)(qb + g);
    }
    __syncthreads();

    uint32_t qf[4][4];
#pragma unroll
    for (int kc = 0; kc < 4; kc++) {
        uint32_t qa = (uint32_t)((wid * 16 + (lane & 15)) * FST + kc * 16
                                 + 8 * (lane >> 4)) * 2;
        LDSM_X4(qf[kc][0], qf[kc][1], qf[kc][2], qf[kc][3], uF + qa);
    }
    __syncthreads();

    float o[8][4];
#pragma unroll
    for (int ni = 0; ni < 8; ni++)
#pragma unroll
        for (int e = 0; e < 4; e++) o[ni][e] = 0.f;
    float m0 = -INFINITY, m1 = -INFINITY, l0 = 0.f, l1 = 0.f;

    const int q8 = lane >> 3;
    const int l7 = lane & 7;

    {
#pragma unroll
        for (int it = 0; it < 4; it++) {
            int L = it * 256 + tid;
            int tsel = L >> 9;
            int r = (L >> 3) & 63, c8 = (L & 7) * 8;
            const __half* srcp = (tsel == 0 ? kb : vb)
                                 + (size_t)r * ROWSTRIDE + c8;
            uint32_t d = uF + (uint32_t)(tsel * KVT + r * FST + c8) * 2;
            CP_ASYNC16(d, srcp);
        }
        CP_COMMIT();
    }

    for (int t = 0; t < S_ / 64; t++) {
        const int st = t & 1;
        if (t + 1 < S_ / 64) {
            const uint32_t sbase = (uint32_t)((st ^ 1) * 2 * KVT) * 2;
#pragma unroll
            for (int it = 0; it < 4; it++) {
                int L = it * 256 + tid;
                int tsel = L >> 9;
                int r = (L >> 3) & 63, c8 = (L & 7) * 8;
                const __half* srcp = (tsel == 0 ? kb : vb)
                                     + (size_t)((t + 1) * 64 + r) * ROWSTRIDE + c8;
                uint32_t d = uF + sbase + (uint32_t)(tsel * KVT + r * FST + c8) * 2;
                CP_ASYNC16(d, srcp);
            }
            CP_COMMIT();
            CP_WAIT(1);
        } else {
            CP_WAIT(0);
        }
        __syncthreads();

        const uint32_t uK = uF + (uint32_t)(st * 2 * KVT) * 2;
        const uint32_t uV = uK + (uint32_t)KVT * 2;

        // S = Q @ K^T over 64 keys
        float s[8][4];
#pragma unroll
        for (int ni = 0; ni < 8; ni++)
#pragma unroll
            for (int e = 0; e < 4; e++) s[ni][e] = 0.f;

#pragma unroll
        for (int kc = 0; kc < 4; kc++) {
#pragma unroll
            for (int ni2 = 0; ni2 < 4; ni2++) {
                uint32_t ka = (uint32_t)(
                    (ni2 * 16 + (q8 >> 1) * 8 + l7) * FST
                    + kc * 16 + (q8 & 1) * 8) * 2;
                uint32_t k4[4];
                LDSM_X4(k4[0], k4[1], k4[2], k4[3], uK + ka);
                mma16816h(s[ni2 * 2], qf[kc], k4);
                mma16816h(s[ni2 * 2 + 1], qf[kc], k4 + 2);
            }
        }

        // Online softmax
        float rm0 = -INFINITY, rm1 = -INFINITY;
#pragma unroll
        for (int ni = 0; ni < 8; ni++) {
            rm0 = fmaxf(rm0, fmaxf(s[ni][0], s[ni][1]));
            rm1 = fmaxf(rm1, fmaxf(s[ni][2], s[ni][3]));
        }
        rm0 = fmaxf(rm0, __shfl_xor_sync(0xffffffffu, rm0, 1));
        rm0 = fmaxf(rm0, __shfl_xor_sync(0xffffffffu, rm0, 2));
        rm1 = fmaxf(rm1, __shfl_xor_sync(0xffffffffu, rm1, 1));
        rm1 = fmaxf(rm1, __shfl_xor_sync(0xffffffffu, rm1, 2));

        float mn0 = fmaxf(m0, rm0), mn1 = fmaxf(m1, rm1);
        float c0 = __expf(m0 - mn0), c1 = __expf(m1 - mn1);
        m0 = mn0; m1 = mn1;

        float rs0 = 0.f, rs1 = 0.f;
        uint32_t ph[8][2];
#pragma unroll
        for (int ni = 0; ni < 8; ni++) {
            s[ni][0] = __expf(s[ni][0] - mn0);
            s[ni][1] = __expf(s[ni][1] - mn0);
            s[ni][2] = __expf(s[ni][2] - mn1);
            s[ni][3] = __expf(s[ni][3] - mn1);
            rs0 += s[ni][0] + s[ni][1];
            rs1 += s[ni][2] + s[ni][3];
            ph[ni][0] = packh(s[ni][0], s[ni][1]);
            ph[ni][1] = packh(s[ni][2], s[ni][3]);
        }
        rs0 += __shfl_xor_sync(0xffffffffu, rs0, 1);
        rs0 += __shfl_xor_sync(0xffffffffu, rs0, 2);
        rs1 += __shfl_xor_sync(0xffffffffu, rs1, 1);
        rs1 += __shfl_xor_sync(0xffffffffu, rs1, 2);
        l0 = l0 * c0 + rs0;
        l1 = l1 * c1 + rs1;

#pragma unroll
        for (int ni = 0; ni < 8; ni++) {
            o[ni][0] *= c0; o[ni][1] *= c0;
            o[ni][2] *= c1; o[ni][3] *= c1;
        }

        // O += P @ V over 64 keys
#pragma unroll
        for (int kc2 = 0; kc2 < 4; kc2++) {
            uint32_t af[4] = {ph[2 * kc2][0], ph[2 * kc2][1],
                              ph[2 * kc2 + 1][0], ph[2 * kc2 + 1][1]};
#pragma unroll
            for (int ni2 = 0; ni2 < 4; ni2++) {
                uint32_t va = (uint32_t)(
                    (kc2 * 16 + (q8 & 1) * 8 + l7) * FST
                    + ni2 * 16 + (q8 >> 1) * 8) * 2;
                uint32_t v4[4];
                LDSM_X4T(v4[0], v4[1], v4[2], v4[3], uV + va);
                mma16816h(o[ni2 * 2], af, v4);
                mma16816h(o[ni2 * 2 + 1], af, v4 + 2);
            }
        }
        __syncthreads();
    }

    // Epilogue: normalize, store fp16
    float inv0 = 1.f / l0, inv1 = 1.f / l1;
    int r0 = q0 + wid * 16 + (lane >> 2);
    size_t obase = ((size_t)bb * S_ + r0) * DM_ + h * DH_;
#pragma unroll
    for (int ni = 0; ni < 8; ni++) {
        int col = ni * 8 + (lane & 3) * 2;
        *(__half2*)(attn16 + obase + col) =
            __float22half2_rn(make_float2(o[ni][0] * inv0, o[ni][1] * inv0));
        *(__half2*)(attn16 + obase + 8 * DM_ + col) =
            __float22half2_rn(make_float2(o[ni][2] * inv1, o[ni][3] * inv1));
    }
}

// ---------------------------------------------------------------------------
extern "C" void kernel_launch(void* const* d_in, const int* in_sizes, int n_in,
                              void* d_out, int out_size)
{
    const float* x    = (const float*)d_in[0];
    const float* Wqkv = (const float*)d_in[1];
    const float* bqkv = (const float*)d_in[2];
    const float* Wout = (const float*)d_in[3];
    const float* bout = (const float*)d_in[4];
    float* out = (float*)d_out;

    __half *qkv16, *x16, *wq16, *wo16, *attn16;
    cudaGetSymbolAddress((void**)&qkv16, g_qkv16);
    cudaGetSymbolAddress((void**)&x16, g_x16);
    cudaGetSymbolAddress((void**)&wq16, g_wq16);
    cudaGetSymbolAddress((void**)&wo16, g_wo16);
    cudaGetSymbolAddress((void**)&attn16, g_attn16);

    cudaFuncSetAttribute(gemm_mma_h16,
                         cudaFuncAttributeMaxDynamicSharedMemorySize,
                         GEMM_SMEM_BYTES);
    cudaFuncSetAttribute(flash_h16, cudaFuncAttributeMaxDynamicSharedMemorySize,
                         FLASH_SMEM_BYTES);

    // 0) convert inputs to fp16
    convert_h16<<<(M_ * DM_ / 4 + 255) / 256, 256>>>(x, x16, M_ * DM_ / 4);
    convert_h16<<<(3 * DM_ * DM_ / 4 + 255) / 256, 256>>>(Wqkv, wq16,
                                                          3 * DM_ * DM_ / 4);
    convert_h16<<<(DM_ * DM_ / 4 + 255) / 256, 256>>>(Wout, wo16,
                                                      DM_ * DM_ / 4);

    // 1) QKV projection + fused bias + RoPE + fp16 convert
    dim3 g1(3 * DM_ / 128, M_ / 128);
    gemm_mma_h16<<<g1, 256, GEMM_SMEM_BYTES>>>(x16, wq16, bqkv,
                                               nullptr, qkv16,
                                               M_, 3 * DM_, DM_);

    // 2) Flash attention (fp16 single-pass), writes fp16 attn
    dim3 g3(S_ / 128, B_ * H_);
    flash_h16<<<g3, 256, FLASH_SMEM_BYTES>>>(qkv16, attn16);

    // 3) Out projection (fp16 single-pass), fp32 output + bias
    dim3 g4(DM_ / 128, M_ / 128);
    gemm_mma_h16<<<g4, 256, GEMM_SMEM_BYTES>>>(attn16, wo16, bout,
                                               out, nullptr,
                                               M_, DM_, DM_);
}